// round 2
// baseline (speedup 1.0000x reference)
#include <cuda_runtime.h>
#include <math.h>

#define B 4
#define S 64
#define D 512
#define H 8
#define DH 64
#define DFF 2048
#define L 2
#define V 32128
#define MAX_ITER 16
#define NEGB (-1e9f)
#define BS (B*S)
#define NKC 64
#define KCH 502   /* 64*502 == 32128 exactly */

// ---------------- device scratch (static, no allocations) ----------------
__device__ float g_x[BS*D];
__device__ float g_h[BS*D];
__device__ float g_q[BS*D];
__device__ float g_k[BS*D];
__device__ float g_v[BS*D];
__device__ float g_ao[BS*D];
__device__ float g_ff[BS*DFF];
__device__ float g_hs[BS*D];
__device__ float g_cK[L*BS*D];
__device__ float g_cV[L*BS*D];
__device__ float g_sK[L*B*MAX_ITER*D];
__device__ float g_sV[L*B*MAX_ITER*D];
__device__ float g_xt[B*D];
__device__ float g_ht[B*D];
__device__ float g_qt[B*D];
__device__ float g_at[B*D];
__device__ float g_fft[B*DFF];
__device__ float g_logits[B*V];
__device__ float g_bias[BS];
__device__ float g_part[NKC*B*D];

// ---------------- kernels ----------------

__global__ void k_embed(const int* ids, const float* mask, const float* emb) {
    int idx = blockIdx.x * blockDim.x + threadIdx.x;  // BS*D
    if (idx < BS*D) {
        int row = idx / D, d = idx % D;
        g_x[idx] = emb[(long)ids[row]*D + d];
    }
    if (idx < BS) g_bias[idx] = (1.0f - mask[idx]) * NEGB;
}

__global__ void k_padembed(const float* emb) {
    int idx = blockIdx.x * blockDim.x + threadIdx.x;  // B*D
    if (idx < B*D) g_xt[idx] = emb[idx % D];   // PAD_ID = 0 -> row 0
}

// RMSNorm: one block per row (D=512), 128 threads
__global__ void k_rms(const float* in, const float* w, float* out) {
    int row = blockIdx.x;
    const float* x = in + (long)row * D;
    float s = 0.f;
    for (int i = threadIdx.x; i < D; i += 128) { float v = x[i]; s += v * v; }
    __shared__ float red[128];
    red[threadIdx.x] = s; __syncthreads();
    for (int o = 64; o; o >>= 1) {
        if (threadIdx.x < o) red[threadIdx.x] += red[threadIdx.x + o];
        __syncthreads();
    }
    float inv = rsqrtf(red[0] / (float)D + 1e-6f);
    for (int i = threadIdx.x; i < D; i += 128)
        out[(long)row * D + i] = x[i] * inv * w[i];
}

// Tiled SGEMM: C[M,N] = A[M,K] @ W[K,N] (+res) (relu). M,N mult of 64, K mult of 16.
#define GBM 64
#define GBN 64
#define GBK 16
__global__ void k_gemm(const float* __restrict__ A, const float* __restrict__ W,
                       const float* res, float* C, int M, int N, int K, int relu) {
    __shared__ float As[GBK][GBM];
    __shared__ float Ws[GBK][GBN];
    int bm = blockIdx.y * GBM, bn = blockIdx.x * GBN;
    int tid = threadIdx.x;               // 256 threads
    int tx = tid % 16, ty = tid / 16;
    float acc[4][4] = {};
    for (int k0 = 0; k0 < K; k0 += GBK) {
        for (int i = tid; i < GBM*GBK; i += 256) {
            int m = i / GBK, k = i % GBK;
            As[k][m] = A[(long)(bm + m) * K + k0 + k];
        }
        for (int i = tid; i < GBK*GBN; i += 256) {
            int k = i / GBN, n = i % GBN;
            Ws[k][n] = W[(long)(k0 + k) * N + bn + n];
        }
        __syncthreads();
#pragma unroll
        for (int k = 0; k < GBK; k++) {
            float a[4], b[4];
#pragma unroll
            for (int i = 0; i < 4; i++) a[i] = As[k][ty*4 + i];
#pragma unroll
            for (int j = 0; j < 4; j++) b[j] = Ws[k][tx*4 + j];
#pragma unroll
            for (int i = 0; i < 4; i++)
#pragma unroll
                for (int j = 0; j < 4; j++) acc[i][j] += a[i] * b[j];
        }
        __syncthreads();
    }
    for (int i = 0; i < 4; i++)
        for (int j = 0; j < 4; j++) {
            int m = bm + ty*4 + i, n = bn + tx*4 + j;
            float vv = acc[i][j];
            if (res)  vv += res[(long)m * N + n];
            if (relu) vv = fmaxf(vv, 0.f);
            C[(long)m * N + n] = vv;
        }
}

// Encoder self-attention, one block per (b,h), 256 threads. 48KB smem.
__global__ void k_encattn(const float* __restrict__ q, const float* __restrict__ k,
                          const float* __restrict__ v) {
    int b = blockIdx.x / H, h = blockIdx.x % H;
    __shared__ float Ks[S][DH], Vs[S][DH], Ps[S][S];
    int tid = threadIdx.x;
    for (int i = tid; i < S*DH; i += 256) {
        int j = i / DH, d = i % DH;
        Ks[j][d] = k[(long)(b*S + j) * D + h*DH + d];
        Vs[j][d] = v[(long)(b*S + j) * D + h*DH + d];
    }
    __syncthreads();
    for (int i = tid; i < S*S; i += 256) {
        int s = i / S, j = i % S;
        const float* qr = q + (long)(b*S + s) * D + h*DH;
        float acc = 0.f;
#pragma unroll
        for (int d = 0; d < DH; d++) acc += qr[d] * Ks[j][d];
        Ps[s][j] = acc * 0.125f + g_bias[b*S + j];
    }
    __syncthreads();
    if (tid < S) {
        int s = tid;
        float mx = -1e30f;
        for (int j = 0; j < S; j++) mx = fmaxf(mx, Ps[s][j]);
        float sum = 0.f;
        for (int j = 0; j < S; j++) { float e = expf(Ps[s][j] - mx); Ps[s][j] = e; sum += e; }
        float r = 1.f / sum;
        for (int j = 0; j < S; j++) Ps[s][j] *= r;
    }
    __syncthreads();
    for (int i = tid; i < S*DH; i += 256) {
        int s = i / DH, d = i % DH;
        float acc = 0.f;
#pragma unroll
        for (int j = 0; j < S; j++) acc += Ps[s][j] * Vs[j][d];
        g_ao[(long)(b*S + s) * D + h*DH + d] = acc;
    }
}

// GEMV with M=4 rows: C[4,N] = A[4,K] @ W[K,N]. dyn smem = 4*K floats.
__global__ void k_gemv4(const float* __restrict__ A, const float* __restrict__ W,
                        const float* res, float* C,
                        int K, int N, int ostride, int rstride, int relu) {
    extern __shared__ float sA[];
    int tid = threadIdx.x;   // 128
    for (int i = tid; i < 4*K; i += 128) sA[i] = A[i];
    __syncthreads();
    int col = blockIdx.x * 128 + tid;
    float a0 = 0, a1 = 0, a2 = 0, a3 = 0;
    for (int kk = 0; kk < K; kk++) {
        float w = __ldg(&W[(long)kk * N + col]);
        a0 += sA[kk] * w;
        a1 += sA[K + kk] * w;
        a2 += sA[2*K + kk] * w;
        a3 += sA[3*K + kk] * w;
    }
    float o[4] = {a0, a1, a2, a3};
#pragma unroll
    for (int r = 0; r < 4; r++) {
        float vv = o[r];
        if (res)  vv += res[(long)r * rstride + col];
        if (relu) vv = fmaxf(vv, 0.f);
        C[(long)r * ostride + col] = vv;
    }
}

// Incremental decoder self-attention (len cached keys), block per (b,h), 64 thr
__global__ void k_selfattn(const float* __restrict__ kc, const float* __restrict__ vc, int len) {
    int b = blockIdx.x / H, h = blockIdx.x % H;
    int tid = threadIdx.x;
    __shared__ float qsh[DH], p[MAX_ITER];
    qsh[tid] = g_qt[b*D + h*DH + tid];
    __syncthreads();
    if (tid < len) {
        const float* kr = kc + (long)(b*MAX_ITER + tid) * D + h*DH;
        float acc = 0.f;
#pragma unroll
        for (int d = 0; d < DH; d++) acc += qsh[d] * kr[d];
        p[tid] = acc * 0.125f;
    }
    __syncthreads();
    if (tid == 0) {
        float mx = -1e30f;
        for (int j = 0; j < len; j++) mx = fmaxf(mx, p[j]);
        float sum = 0.f;
        for (int j = 0; j < len; j++) { float e = expf(p[j] - mx); p[j] = e; sum += e; }
        float r = 1.f / sum;
        for (int j = 0; j < len; j++) p[j] *= r;
    }
    __syncthreads();
    float acc = 0.f;
    for (int j = 0; j < len; j++)
        acc += p[j] * vc[(long)(b*MAX_ITER + j) * D + h*DH + tid];
    g_at[b*D + h*DH + tid] = acc;
}

// Decoder cross-attention over S=64 cached enc K/V, block per (b,h), 64 thr
__global__ void k_crossattn(const float* __restrict__ kc, const float* __restrict__ vc) {
    int b = blockIdx.x / H, h = blockIdx.x % H;
    int tid = threadIdx.x;
    __shared__ float qsh[DH], p[S];
    qsh[tid] = g_qt[b*D + h*DH + tid];
    __syncthreads();
    const float* kr = kc + (long)(b*S + tid) * D + h*DH;
    float acc = 0.f;
#pragma unroll
    for (int d = 0; d < DH; d++) acc += qsh[d] * kr[d];
    p[tid] = acc * 0.125f + g_bias[b*S + tid];
    __syncthreads();
    if (tid == 0) {
        float mx = -1e30f;
        for (int j = 0; j < S; j++) mx = fmaxf(mx, p[j]);
        float sum = 0.f;
        for (int j = 0; j < S; j++) { float e = expf(p[j] - mx); p[j] = e; sum += e; }
        float r = 1.f / sum;
        for (int j = 0; j < S; j++) p[j] *= r;
    }
    __syncthreads();
    float o = 0.f;
    for (int j = 0; j < S; j++)
        o += p[j] * vc[(long)(b*S + j) * D + h*DH + tid];
    g_at[b*D + h*DH + tid] = o;
}

// Softmax + argmax over V; write probs into d_out slice; write pad flag.
__global__ void k_softmax(float* out, int iter) {
    int b = blockIdx.x;
    const float* lg = g_logits + (long)b * V;
    float* probs = out + (long)(b*MAX_ITER + iter) * V;
    int tid = threadIdx.x;   // 256
    __shared__ float smax[256]; __shared__ int sidx[256]; __shared__ float ssum[256];
    float mx = -1e30f; int mi = 0;
    for (int i = tid; i < V; i += 256) { float vv = lg[i]; if (vv > mx) { mx = vv; mi = i; } }
    smax[tid] = mx; sidx[tid] = mi; __syncthreads();
    for (int o = 128; o; o >>= 1) {
        if (tid < o) {
            if (smax[tid+o] > smax[tid] ||
                (smax[tid+o] == smax[tid] && sidx[tid+o] < sidx[tid])) {
                smax[tid] = smax[tid+o]; sidx[tid] = sidx[tid+o];
            }
        }
        __syncthreads();
    }
    float M = smax[0]; int best = sidx[0];
    float s = 0.f;
    for (int i = tid; i < V; i += 256) { float e = expf(lg[i] - M); probs[i] = e; s += e; }
    ssum[tid] = s; __syncthreads();
    for (int o = 128; o; o >>= 1) {
        if (tid < o) ssum[tid] += ssum[tid+o];
        __syncthreads();
    }
    float r = 1.f / ssum[0];
    for (int i = tid; i < V; i += 256) probs[i] *= r;
    if (tid == 0)
        out[(long)B*MAX_ITER*V + b*MAX_ITER + iter] = (best == 0) ? 1.0f : 0.0f;
}

// y_next = probs @ emb, split-K partials (deterministic), grid (4 colblocks, NKC kchunks)
__global__ void k_pe_partial(const float* __restrict__ Pbase, const float* __restrict__ emb) {
    int cb = blockIdx.x, kc = blockIdx.y;
    int tid = threadIdx.x;   // 128
    int col = cb * 128 + tid;
    int k0 = kc * KCH;
    __shared__ float sp[4][KCH];
    for (int i = tid; i < 4*KCH; i += 128) {
        int r = i / KCH, kk = i % KCH;
        sp[r][kk] = Pbase[(long)r * (MAX_ITER*(long)V) + k0 + kk];
    }
    __syncthreads();
    float a0 = 0, a1 = 0, a2 = 0, a3 = 0;
    for (int kk = 0; kk < KCH; kk++) {
        float w = __ldg(&emb[(long)(k0 + kk) * D + col]);
        a0 += sp[0][kk] * w; a1 += sp[1][kk] * w;
        a2 += sp[2][kk] * w; a3 += sp[3][kk] * w;
    }
    float* pp = g_part + (long)kc * (B*D);
    pp[0*D + col] = a0; pp[1*D + col] = a1; pp[2*D + col] = a2; pp[3*D + col] = a3;
}

__global__ void k_pe_reduce() {
    int i = blockIdx.x * blockDim.x + threadIdx.x;
    if (i < B*D) {
        float s = 0.f;
        for (int kc = 0; kc < NKC; kc++) s += g_part[(long)kc * (B*D) + i];
        g_xt[i] = s;
    }
}

// ---------------- host orchestration ----------------
extern "C" void kernel_launch(void* const* d_in, const int* in_sizes, int n_in,
                              void* d_out, int out_size) {
    const int*   ids   = (const int*)  d_in[0];
    const float* mask  = (const float*)d_in[1];
    const float* emb   = (const float*)d_in[2];
    const float* enc_wq = (const float*)d_in[3];
    const float* enc_wk = (const float*)d_in[4];
    const float* enc_wv = (const float*)d_in[5];
    const float* enc_wo = (const float*)d_in[6];
    const float* enc_ln1 = (const float*)d_in[7];
    const float* enc_w1 = (const float*)d_in[8];
    const float* enc_w2 = (const float*)d_in[9];
    const float* enc_ln2 = (const float*)d_in[10];
    const float* enc_lnf = (const float*)d_in[11];
    const float* dec_sq = (const float*)d_in[12];
    const float* dec_sk = (const float*)d_in[13];
    const float* dec_sv = (const float*)d_in[14];
    const float* dec_so = (const float*)d_in[15];
    const float* dec_ln1 = (const float*)d_in[16];
    const float* dec_cq = (const float*)d_in[17];
    const float* dec_ck = (const float*)d_in[18];
    const float* dec_cv = (const float*)d_in[19];
    const float* dec_co = (const float*)d_in[20];
    const float* dec_ln2 = (const float*)d_in[21];
    const float* dec_w1 = (const float*)d_in[22];
    const float* dec_w2 = (const float*)d_in[23];
    const float* dec_ln3 = (const float*)d_in[24];
    const float* dec_lnf = (const float*)d_in[25];
    const float* lm_head = (const float*)d_in[26];
    float* out = (float*)d_out;

    // symbol addresses (host-side, cheap, capture-safe)
    float *px, *ph, *pq, *pk, *pv, *pao, *pff, *phs, *pcK, *pcV, *psK, *psV;
    float *pxt, *pht, *pqt, *pat, *pfft, *plog;
    cudaGetSymbolAddress((void**)&px,  g_x);
    cudaGetSymbolAddress((void**)&ph,  g_h);
    cudaGetSymbolAddress((void**)&pq,  g_q);
    cudaGetSymbolAddress((void**)&pk,  g_k);
    cudaGetSymbolAddress((void**)&pv,  g_v);
    cudaGetSymbolAddress((void**)&pao, g_ao);
    cudaGetSymbolAddress((void**)&pff, g_ff);
    cudaGetSymbolAddress((void**)&phs, g_hs);
    cudaGetSymbolAddress((void**)&pcK, g_cK);
    cudaGetSymbolAddress((void**)&pcV, g_cV);
    cudaGetSymbolAddress((void**)&psK, g_sK);
    cudaGetSymbolAddress((void**)&psV, g_sV);
    cudaGetSymbolAddress((void**)&pxt, g_xt);
    cudaGetSymbolAddress((void**)&pht, g_ht);
    cudaGetSymbolAddress((void**)&pqt, g_qt);
    cudaGetSymbolAddress((void**)&pat, g_at);
    cudaGetSymbolAddress((void**)&pfft, g_fft);
    cudaGetSymbolAddress((void**)&plog, g_logits);

    // ---- encoder ----
    k_embed<<<(BS*D + 255)/256, 256>>>(ids, mask, emb);
    for (int l = 0; l < L; l++) {
        k_rms<<<BS, 128>>>(px, enc_ln1 + l*D, ph);
        k_gemm<<<dim3(D/64, BS/64), 256>>>(ph, enc_wq + (long)l*D*D, nullptr, pq, BS, D, D, 0);
        k_gemm<<<dim3(D/64, BS/64), 256>>>(ph, enc_wk + (long)l*D*D, nullptr, pk, BS, D, D, 0);
        k_gemm<<<dim3(D/64, BS/64), 256>>>(ph, enc_wv + (long)l*D*D, nullptr, pv, BS, D, D, 0);
        k_encattn<<<B*H, 256>>>(pq, pk, pv);
        k_gemm<<<dim3(D/64, BS/64), 256>>>(pao, enc_wo + (long)l*D*D, px, px, BS, D, D, 0);
        k_rms<<<BS, 128>>>(px, enc_ln2 + l*D, ph);
        k_gemm<<<dim3(DFF/64, BS/64), 256>>>(ph, enc_w1 + (long)l*D*DFF, nullptr, pff, BS, DFF, D, 1);
        k_gemm<<<dim3(D/64, BS/64), 256>>>(pff, enc_w2 + (long)l*DFF*D, px, px, BS, D, DFF, 0);
    }
    k_rms<<<BS, 128>>>(px, enc_lnf, phs);

    // precompute cross-attention K/V (hs is fixed across all decode iterations)
    for (int l = 0; l < L; l++) {
        k_gemm<<<dim3(D/64, BS/64), 256>>>(phs, dec_ck + (long)l*D*D, nullptr, pcK + (long)l*BS*D, BS, D, D, 0);
        k_gemm<<<dim3(D/64, BS/64), 256>>>(phs, dec_cv + (long)l*D*D, nullptr, pcV + (long)l*BS*D, BS, D, D, 0);
    }

    // ---- decoder: exact incremental decoding with KV cache ----
    k_padembed<<<(B*D + 255)/256, 256>>>(emb);
    size_t smD  = 4 * D  * sizeof(float);   // 8KB
    size_t smFF = 4 * DFF * sizeof(float);  // 32KB

    for (int it = 0; it < MAX_ITER; it++) {
        int len = it + 1;
        for (int l = 0; l < L; l++) {
            float* kcb = psK + (long)l*B*MAX_ITER*D;
            float* vcb = psV + (long)l*B*MAX_ITER*D;
            // self-attention
            k_rms<<<B, 128>>>(pxt, dec_ln1 + l*D, pht);
            k_gemv4<<<D/128, 128, smD>>>(pht, dec_sq + (long)l*D*D, nullptr, pqt, D, D, D, D, 0);
            k_gemv4<<<D/128, 128, smD>>>(pht, dec_sk + (long)l*D*D, nullptr, kcb + (long)it*D, D, D, MAX_ITER*D, 0, 0);
            k_gemv4<<<D/128, 128, smD>>>(pht, dec_sv + (long)l*D*D, nullptr, vcb + (long)it*D, D, D, MAX_ITER*D, 0, 0);
            k_selfattn<<<B*H, 64>>>(kcb, vcb, len);
            k_gemv4<<<D/128, 128, smD>>>(pat, dec_so + (long)l*D*D, pxt, pxt, D, D, D, D, 0);
            // cross-attention (cached K/V)
            k_rms<<<B, 128>>>(pxt, dec_ln2 + l*D, pht);
            k_gemv4<<<D/128, 128, smD>>>(pht, dec_cq + (long)l*D*D, nullptr, pqt, D, D, D, D, 0);
            k_crossattn<<<B*H, 64>>>(pcK + (long)l*BS*D, pcV + (long)l*BS*D);
            k_gemv4<<<D/128, 128, smD>>>(pat, dec_co + (long)l*D*D, pxt, pxt, D, D, D, D, 0);
            // FFN
            k_rms<<<B, 128>>>(pxt, dec_ln3 + l*D, pht);
            k_gemv4<<<DFF/128, 128, smD>>>(pht, dec_w1 + (long)l*D*DFF, nullptr, pfft, D, DFF, DFF, 0, 1);
            k_gemv4<<<D/128, 128, smFF>>>(pfft, dec_w2 + (long)l*DFF*D, pxt, pxt, DFF, D, D, D, 0);
        }
        k_rms<<<B, 128>>>(pxt, dec_lnf, pht);
        k_gemv4<<<V/128, 128, smD>>>(pht, lm_head, nullptr, plog, D, V, V, 0, 0);
        k_softmax<<<B, 256>>>(out, it);
        if (it + 1 < MAX_ITER) {
            k_pe_partial<<<dim3(D/128, NKC), 128>>>(out + (long)it*V, emb);
            k_pe_reduce<<<(B*D + 127)/128, 128>>>();
        }
    }
}

// round 3
// speedup vs baseline: 5.9553x; 5.9553x over previous
#include <cuda_runtime.h>
#include <math.h>

#define B 4
#define S 64
#define D 512
#define H 8
#define DH 64
#define DFF 2048
#define L 2
#define V 32128
#define MAX_ITER 16
#define NEGB (-1e9f)
#define BS (B*S)
#define NB 148
#define NT 256
#define NKC 8
#define PEK (V/NKC)      /* 4016 */
#define PEKW (PEK/8)     /* 502  */

// ---------------- device scratch ----------------
__device__ float g_x[BS*D];
__device__ float g_h[BS*D];
__device__ float g_q[BS*D];
__device__ float g_k[BS*D];
__device__ float g_v[BS*D];
__device__ float g_ao[BS*D];
__device__ float g_ff[BS*DFF];
__device__ float g_hs[BS*D];
__device__ float g_cK[L*BS*D];
__device__ float g_cV[L*BS*D];
__device__ float g_sK[L*B*MAX_ITER*D];
__device__ float g_sV[L*B*MAX_ITER*D];
__device__ float g_xt[B*D];
__device__ float g_qt[B*D];
__device__ float g_at[B*D];
__device__ float g_fft[B*DFF];
__device__ float g_logits[B*V];
__device__ float g_bias[BS];
__device__ float g_part[NKC*B*D];
__device__ unsigned g_barcnt;
__device__ unsigned g_barsense;

// ---------------- grid barrier (all NB blocks co-resident) ----------------
__device__ __forceinline__ void gridbar() {
    __syncthreads();
    if (threadIdx.x == 0) {
        __threadfence();
        unsigned cur = *(volatile unsigned*)&g_barsense;
        if (atomicAdd(&g_barcnt, 1u) == NB - 1u) {
            g_barcnt = 0u;
            __threadfence();
            *(volatile unsigned*)&g_barsense = cur + 1u;
        } else {
            while (*(volatile unsigned*)&g_barsense == cur) { }
        }
        __threadfence();   // scope>=gpu -> invalidates this SM's L1 (fresh reads)
    }
    __syncthreads();
}

// ---------------- encoder tiled GEMM phase: C[M,N] = A@W (+res)(relu) -------
__device__ void gemm_phase(char* sb, const float* __restrict__ A,
                           const float* __restrict__ W, const float* res,
                           float* C, int M, int N, int K, int relu) {
    float* As = (float*)sb;            // [32][32] As[k][m]
    float* Ws = (float*)(sb + 4096);   // [32][32] Ws[k][n]
    int tid = threadIdx.x;
    int n = tid & 31;
    int mg = tid >> 5;                 // row group 0..7 (rows mg*4..+3)
    int tM = M >> 5, tN = N >> 5;
    for (int t = blockIdx.x; t < tM * tN; t += NB) {
        int bm = (t / tN) << 5, bn = (t % tN) << 5;
        float a0=0.f,a1=0.f,a2=0.f,a3=0.f;
        for (int k0 = 0; k0 < K; k0 += 32) {
            {   // load A tile (float4, transpose into As[k][m])
                int m = (tid*4) >> 5, k = (tid*4) & 31;
                float4 av = *(const float4*)(A + (long)(bm+m)*K + k0 + k);
                As[(k+0)*32 + m] = av.x; As[(k+1)*32 + m] = av.y;
                As[(k+2)*32 + m] = av.z; As[(k+3)*32 + m] = av.w;
            }
#pragma unroll
            for (int i = 0; i < 4; i++) {
                int idx = tid + i*NT;
                int k = idx >> 5, nn = idx & 31;
                Ws[k*32 + nn] = W[(long)(k0+k)*N + bn + nn];
            }
            __syncthreads();
#pragma unroll
            for (int k = 0; k < 32; k++) {
                float w = Ws[k*32 + n];
                a0 += As[k*32 + mg*4+0]*w;
                a1 += As[k*32 + mg*4+1]*w;
                a2 += As[k*32 + mg*4+2]*w;
                a3 += As[k*32 + mg*4+3]*w;
            }
            __syncthreads();
        }
        float accs[4] = {a0,a1,a2,a3};
#pragma unroll
        for (int i = 0; i < 4; i++) {
            long m = bm + mg*4 + i;
            float vv = accs[i];
            if (res)  vv += res[m*N + bn + n];
            if (relu) vv = fmaxf(vv, 0.f);
            C[m*N + bn + n] = vv;
        }
    }
}

// ---------------- RMSNorm phase (rows x D) ----------------
__device__ void rms_phase(char* sb, const float* in, const float* w,
                          float* out, int rows) {
    float* red = (float*)sb;  // 256
    int tid = threadIdx.x;
    for (int r = blockIdx.x; r < rows; r += NB) {
        const float* x = in + (long)r * D;
        float s = 0.f;
        for (int i = tid; i < D; i += NT) { float v = x[i]; s += v*v; }
        red[tid] = s; __syncthreads();
        for (int o = 128; o; o >>= 1) {
            if (tid < o) red[tid] += red[tid+o];
            __syncthreads();
        }
        float inv = rsqrtf(red[0] / (float)D + 1e-6f);
        __syncthreads();
        for (int i = tid; i < D; i += NT)
            out[(long)r*D + i] = x[i] * inv * w[i];
        __syncthreads();
    }
}

// ---------------- encoder attention phase ----------------
__device__ void enc_attn_phase(char* sb) {
    float* Ks = (float*)sb;            // 64*64
    float* Ps = (float*)(sb + 16384);  // 64*64
    int tid = threadIdx.x;
    for (int t = blockIdx.x; t < B*H; t += NB) {
        int b = t / H, h = t % H;
        for (int i = tid; i < S*DH; i += NT) {
            int j = i / DH, d = i % DH;
            Ks[j*DH + d] = g_k[(long)(b*S + j)*D + h*DH + d];
        }
        __syncthreads();
        for (int i = tid; i < S*S; i += NT) {
            int s = i / S, j = i % S;
            const float* qr = g_q + (long)(b*S + s)*D + h*DH;
            float acc = 0.f;
#pragma unroll
            for (int d = 0; d < DH; d++) acc += qr[d] * Ks[j*DH + d];
            Ps[s*S + j] = acc * 0.125f + g_bias[b*S + j];
        }
        __syncthreads();
        if (tid < S) {
            int s = tid;
            float mx = -1e30f;
            for (int j = 0; j < S; j++) mx = fmaxf(mx, Ps[s*S+j]);
            float sum = 0.f;
            for (int j = 0; j < S; j++) { float e = expf(Ps[s*S+j]-mx); Ps[s*S+j]=e; sum+=e; }
            float r = 1.f / sum;
            for (int j = 0; j < S; j++) Ps[s*S+j] *= r;
        }
        __syncthreads();
        for (int i = tid; i < S*DH; i += NT) {
            int s = i / DH, d = i % DH;
            float acc = 0.f;
            for (int j = 0; j < S; j++)
                acc += Ps[s*S+j] * g_v[(long)(b*S + j)*D + h*DH + d];
            g_ao[(long)(b*S + s)*D + h*DH + d] = acc;
        }
        __syncthreads();
    }
}

// ---------------- decoder gemv machinery ----------------
// stage x (B rows x K) into smem, optionally RMS-normalized (K==512 when lnw!=0)
__device__ void stage_x(char* sb, const float* x, const float* lnw, int K) {
    float* xs  = (float*)sb;
    float* red = (float*)(sb + 32768);
    int tid = threadIdx.x;
    if (lnw) {  // K == 512
        int base = tid * 8;
        int b = base >> 9;
        float vals[8];
        float s = 0.f;
#pragma unroll
        for (int j = 0; j < 8; j++) { vals[j] = x[base+j]; s += vals[j]*vals[j]; }
        red[tid] = s; __syncthreads();
        if (tid < 4) {
            float t = 0.f;
            for (int i = 0; i < 64; i++) t += red[tid*64 + i];
            red[1000 + tid] = rsqrtf(t / 512.0f + 1e-6f);
        }
        __syncthreads();
        float inv = red[1000 + b];
#pragma unroll
        for (int j = 0; j < 8; j++)
            xs[base+j] = vals[j] * inv * lnw[(base+j) & 511];
    } else {
        for (int i = tid; i < 4*K; i += NT) xs[i] = x[i];
    }
    __syncthreads();
}

// one 32-col block of out[4,N] = xs[4,K] @ W[K,N]; 8-way K split + smem reduce
__device__ __forceinline__ void gemv_one(char* sb, int K, int N,
        const float* __restrict__ W, int cb, float* outp, long ostride,
        const float* res, long rstride, int relu) {
    float* xs  = (float*)sb;
    float* red = (float*)(sb + 32768);
    int tid = threadIdx.x;
    int c = tid & 31, ws = tid >> 5;
    int Kc = K >> 3;
    int col = (cb << 5) + c;
    const float* Wp = W + (long)ws * Kc * N + col;
    const float* x0 = xs + ws * Kc;
    float a0=0.f,a1=0.f,a2=0.f,a3=0.f;
#pragma unroll 8
    for (int kk = 0; kk < Kc; kk++) {
        float w = Wp[(long)kk * N];
        a0 += x0[kk]       * w;
        a1 += x0[K + kk]   * w;
        a2 += x0[2*K + kk] * w;
        a3 += x0[3*K + kk] * w;
    }
    red[tid*4+0]=a0; red[tid*4+1]=a1; red[tid*4+2]=a2; red[tid*4+3]=a3;
    __syncthreads();
    if (tid < 128) {
        int cc = tid & 31, b = tid >> 5;
        float s = 0.f;
#pragma unroll
        for (int w8 = 0; w8 < 8; w8++) s += red[((w8<<5)+cc)*4 + b];
        int ocol = (cb << 5) + cc;
        if (res)  s += res[(long)b*rstride + ocol];
        if (relu) s = fmaxf(s, 0.f);
        outp[(long)b*ostride + ocol] = s;
    }
    __syncthreads();
}

__device__ void gemv_mat(char* sb, int K, int N, const float* W,
                         float* outp, long ostride, const float* res,
                         long rstride, int relu) {
    int ncb = N >> 5;
    for (int cb = blockIdx.x; cb < ncb; cb += NB)
        gemv_one(sb, K, N, W, cb, outp, ostride, res, rstride, relu);
}

__device__ void gemv3(char* sb, const float* W0, const float* W1, const float* W2,
                      float* o0, long os0, float* o1, long os1, float* o2, long os2) {
    int ncb = D >> 5;   // 16
    for (int t = blockIdx.x; t < 3*ncb; t += NB) {
        int m = t / ncb, cb = t % ncb;
        const float* W = (m==0) ? W0 : (m==1) ? W1 : W2;
        float* op      = (m==0) ? o0 : (m==1) ? o1 : o2;
        long os        = (m==0) ? os0 : (m==1) ? os1 : os2;
        gemv_one(sb, D, D, W, cb, op, os, 0, 0, 0);
    }
}

// ---------------- decoder attention phases ----------------
__device__ void dec_selfattn(char* sb, const float* kc, const float* vc, int len) {
    float* qsh = (float*)sb;
    float* p   = qsh + 64;
    int tid = threadIdx.x;
    for (int t = blockIdx.x; t < B*H; t += NB) {
        int b = t >> 3, h = t & 7;
        if (tid < 64) qsh[tid] = g_qt[b*D + h*DH + tid];
        __syncthreads();
        if (tid < len) {
            const float* kr = kc + (long)(b*MAX_ITER + tid)*D + h*DH;
            float acc = 0.f;
#pragma unroll
            for (int d = 0; d < DH; d++) acc += qsh[d]*kr[d];
            p[tid] = acc * 0.125f;
        }
        __syncthreads();
        if (tid == 0) {
            float mx = -1e30f;
            for (int j = 0; j < len; j++) mx = fmaxf(mx, p[j]);
            float sum = 0.f;
            for (int j = 0; j < len; j++) { float e = expf(p[j]-mx); p[j]=e; sum+=e; }
            float r = 1.f/sum;
            for (int j = 0; j < len; j++) p[j] *= r;
        }
        __syncthreads();
        if (tid < 64) {
            float acc = 0.f;
            for (int j = 0; j < len; j++)
                acc += p[j] * vc[(long)(b*MAX_ITER + j)*D + h*DH + tid];
            g_at[b*D + h*DH + tid] = acc;
        }
        __syncthreads();
    }
}

__device__ void dec_crossattn(char* sb, const float* kc, const float* vc) {
    float* qsh = (float*)sb;
    float* p   = qsh + 64;
    int tid = threadIdx.x;
    for (int t = blockIdx.x; t < B*H; t += NB) {
        int b = t >> 3, h = t & 7;
        if (tid < 64) qsh[tid] = g_qt[b*D + h*DH + tid];
        __syncthreads();
        if (tid < S) {
            const float* kr = kc + (long)(b*S + tid)*D + h*DH;
            float acc = 0.f;
#pragma unroll
            for (int d = 0; d < DH; d++) acc += qsh[d]*kr[d];
            p[tid] = acc * 0.125f + g_bias[b*S + tid];
        }
        __syncthreads();
        if (tid == 0) {
            float mx = -1e30f;
            for (int j = 0; j < S; j++) mx = fmaxf(mx, p[j]);
            float sum = 0.f;
            for (int j = 0; j < S; j++) { float e = expf(p[j]-mx); p[j]=e; sum+=e; }
            float r = 1.f/sum;
            for (int j = 0; j < S; j++) p[j] *= r;
        }
        __syncthreads();
        if (tid < 64) {
            float acc = 0.f;
            for (int j = 0; j < S; j++)
                acc += p[j] * vc[(long)(b*S + j)*D + h*DH + tid];
            g_at[b*D + h*DH + tid] = acc;
        }
        __syncthreads();
    }
}

// ---------------- softmax + argmax over V ----------------
__device__ void softmax_phase(char* sb, float* out, int it) {
    float* smax = (float*)sb;
    float* ssum = smax + 256;
    int*   sidx = (int*)(ssum + 256);
    int tid = threadIdx.x;
    for (int b = blockIdx.x; b < B; b += NB) {
        const float* lg = g_logits + (long)b*V;
        float* probs = out + (long)(b*MAX_ITER + it)*V;
        float mx = -1e30f; int mi = 0;
        for (int i = tid; i < V; i += NT) { float v = lg[i]; if (v > mx) { mx=v; mi=i; } }
        smax[tid]=mx; sidx[tid]=mi; __syncthreads();
        for (int o = 128; o; o >>= 1) {
            if (tid < o) {
                if (smax[tid+o] > smax[tid] ||
                    (smax[tid+o] == smax[tid] && sidx[tid+o] < sidx[tid])) {
                    smax[tid]=smax[tid+o]; sidx[tid]=sidx[tid+o];
                }
            }
            __syncthreads();
        }
        float M = smax[0]; int best = sidx[0];
        __syncthreads();
        float s = 0.f;
        for (int i = tid; i < V; i += NT) { float e = expf(lg[i]-M); probs[i]=e; s+=e; }
        ssum[tid] = s; __syncthreads();
        for (int o = 128; o; o >>= 1) {
            if (tid < o) ssum[tid] += ssum[tid+o];
            __syncthreads();
        }
        float r = 1.f / ssum[0];
        for (int i = tid; i < V; i += NT) probs[i] *= r;
        if (tid == 0)
            out[(long)B*MAX_ITER*V + b*MAX_ITER + it] = (best == 0) ? 1.0f : 0.0f;
        __syncthreads();
    }
}

// ---------------- probs @ emb (block split-K partials) ----------------
__device__ void pe_partial(char* sb, const float* __restrict__ probs,
                           const float* __restrict__ emb, long rstride) {
    float* red = (float*)(sb + 32768);
    int tid = threadIdx.x;
    int c = tid & 31, ws = tid >> 5;
    for (int t = blockIdx.x; t < 16*NKC; t += NB) {
        int cb = t & 15, kc = t >> 4;
        int col = cb*32 + c;
        int k0 = kc*PEK + ws*PEKW;
        const float* ep = emb + (long)k0*D + col;
        const float* p0 = probs + k0;
        float a0=0.f,a1=0.f,a2=0.f,a3=0.f;
#pragma unroll 4
        for (int kk = 0; kk < PEKW; kk++) {
            float w = ep[(long)kk*D];
            a0 += p0[kk]            * w;
            a1 += p0[rstride   + kk]* w;
            a2 += p0[2*rstride + kk]* w;
            a3 += p0[3*rstride + kk]* w;
        }
        red[tid*4+0]=a0; red[tid*4+1]=a1; red[tid*4+2]=a2; red[tid*4+3]=a3;
        __syncthreads();
        if (tid < 128) {
            int cc = tid & 31, b = tid >> 5;
            float s = 0.f;
#pragma unroll
            for (int w8 = 0; w8 < 8; w8++) s += red[((w8<<5)+cc)*4 + b];
            g_part[((long)kc*B + b)*D + cb*32 + cc] = s;
        }
        __syncthreads();
    }
}

__device__ void pe_reduce() {
    int tid = threadIdx.x;
    for (int i = blockIdx.x*NT + tid; i < B*D; i += NB*NT) {
        float s = 0.f;
#pragma unroll
        for (int kc = 0; kc < NKC; kc++) s += g_part[(long)kc*B*D + i];
        g_xt[i] = s;
    }
}

// ---------------- megakernel ----------------
__global__ void __launch_bounds__(NT, 1) mega(
    const int* ids, const float* mask, const float* emb,
    const float* enc_wq, const float* enc_wk, const float* enc_wv, const float* enc_wo,
    const float* enc_ln1, const float* enc_w1, const float* enc_w2,
    const float* enc_ln2, const float* enc_lnf,
    const float* dec_sq, const float* dec_sk, const float* dec_sv, const float* dec_so,
    const float* dec_ln1, const float* dec_cq, const float* dec_ck, const float* dec_cv,
    const float* dec_co, const float* dec_ln2, const float* dec_w1, const float* dec_w2,
    const float* dec_ln3, const float* dec_lnf, const float* lm_head, float* out)
{
    __shared__ __align__(16) float sbf[(32768 + 4096)/4];
    char* sb = (char*)sbf;
    int tid = threadIdx.x;

    // ---- E0: embedding + bias + decoder init ----
    for (int i = blockIdx.x*NT + tid; i < BS*D; i += NB*NT) {
        int row = i / D, d = i % D;
        g_x[i] = emb[(long)ids[row]*D + d];
    }
    for (int i = blockIdx.x*NT + tid; i < BS; i += NB*NT)
        g_bias[i] = (1.0f - mask[i]) * NEGB;
    for (int i = blockIdx.x*NT + tid; i < B*D; i += NB*NT)
        g_xt[i] = emb[i % D];        // PAD_ID = 0
    gridbar();

    // ---- encoder ----
    for (int l = 0; l < L; l++) {
        rms_phase(sb, g_x, enc_ln1 + l*D, g_h, BS); gridbar();
        gemm_phase(sb, g_h, enc_wq + (long)l*D*D, 0, g_q, BS, D, D, 0);
        gemm_phase(sb, g_h, enc_wk + (long)l*D*D, 0, g_k, BS, D, D, 0);
        gemm_phase(sb, g_h, enc_wv + (long)l*D*D, 0, g_v, BS, D, D, 0);
        gridbar();
        enc_attn_phase(sb); gridbar();
        gemm_phase(sb, g_ao, enc_wo + (long)l*D*D, g_x, g_x, BS, D, D, 0); gridbar();
        rms_phase(sb, g_x, enc_ln2 + l*D, g_h, BS); gridbar();
        gemm_phase(sb, g_h, enc_w1 + (long)l*D*DFF, 0, g_ff, BS, DFF, D, 1); gridbar();
        gemm_phase(sb, g_ff, enc_w2 + (long)l*DFF*D, g_x, g_x, BS, D, DFF, 0); gridbar();
    }
    rms_phase(sb, g_x, enc_lnf, g_hs, BS); gridbar();
    for (int l = 0; l < L; l++) {
        gemm_phase(sb, g_hs, dec_ck + (long)l*D*D, 0, g_cK + (long)l*BS*D, BS, D, D, 0);
        gemm_phase(sb, g_hs, dec_cv + (long)l*D*D, 0, g_cV + (long)l*BS*D, BS, D, D, 0);
    }
    gridbar();

    // ---- decoder: incremental with KV cache ----
    for (int it = 0; it < MAX_ITER; it++) {
        int len = it + 1;
        for (int l = 0; l < L; l++) {
            float* kcb = g_sK + (long)l*B*MAX_ITER*D;
            float* vcb = g_sV + (long)l*B*MAX_ITER*D;
            // self-attention QKV (fused rms1)
            stage_x(sb, g_xt, dec_ln1 + l*D, D);
            gemv3(sb, dec_sq + (long)l*D*D, dec_sk + (long)l*D*D, dec_sv + (long)l*D*D,
                  g_qt, D, kcb + (long)it*D, (long)MAX_ITER*D, vcb + (long)it*D, (long)MAX_ITER*D);
            gridbar();
            dec_selfattn(sb, kcb, vcb, len); gridbar();
            stage_x(sb, g_at, 0, D);
            gemv_mat(sb, D, D, dec_so + (long)l*D*D, g_xt, D, g_xt, D, 0); gridbar();
            // cross-attention (fused rms2)
            stage_x(sb, g_xt, dec_ln2 + l*D, D);
            gemv_mat(sb, D, D, dec_cq + (long)l*D*D, g_qt, D, 0, 0, 0); gridbar();
            dec_crossattn(sb, g_cK + (long)l*BS*D, g_cV + (long)l*BS*D); gridbar();
            stage_x(sb, g_at, 0, D);
            gemv_mat(sb, D, D, dec_co + (long)l*D*D, g_xt, D, g_xt, D, 0); gridbar();
            // FFN (fused rms3)
            stage_x(sb, g_xt, dec_ln3 + l*D, D);
            gemv_mat(sb, D, DFF, dec_w1 + (long)l*D*DFF, g_fft, DFF, 0, 0, 1); gridbar();
            stage_x(sb, g_fft, 0, DFF);
            gemv_mat(sb, DFF, D, dec_w2 + (long)l*DFF*D, g_xt, D, g_xt, D, 0); gridbar();
        }
        // lm head (fused final rms)
        stage_x(sb, g_xt, dec_lnf, D);
        gemv_mat(sb, D, V, lm_head, g_logits, V, 0, 0, 0); gridbar();
        softmax_phase(sb, out, it); gridbar();
        if (it + 1 < MAX_ITER) {
            pe_partial(sb, out + (long)it*V, emb, (long)MAX_ITER*V); gridbar();
            pe_reduce(); gridbar();
        }
    }
}

// ---------------- host ----------------
extern "C" void kernel_launch(void* const* d_in, const int* in_sizes, int n_in,
                              void* d_out, int out_size) {
    mega<<<NB, NT>>>(
        (const int*)d_in[0], (const float*)d_in[1], (const float*)d_in[2],
        (const float*)d_in[3], (const float*)d_in[4], (const float*)d_in[5],
        (const float*)d_in[6], (const float*)d_in[7], (const float*)d_in[8],
        (const float*)d_in[9], (const float*)d_in[10], (const float*)d_in[11],
        (const float*)d_in[12], (const float*)d_in[13], (const float*)d_in[14],
        (const float*)d_in[15], (const float*)d_in[16], (const float*)d_in[17],
        (const float*)d_in[18], (const float*)d_in[19], (const float*)d_in[20],
        (const float*)d_in[21], (const float*)d_in[22], (const float*)d_in[23],
        (const float*)d_in[24], (const float*)d_in[25], (const float*)d_in[26],
        (float*)d_out);
}

// round 4
// speedup vs baseline: 9.0213x; 1.5148x over previous
#include <cuda_runtime.h>
#include <math.h>

#define B 4
#define S 64
#define D 512
#define H 8
#define DH 64
#define DFF 2048
#define L 2
#define V 32128
#define MAX_ITER 16
#define NEGB (-1e9f)
#define BS (B*S)
#define NB 148
#define NT 256
#define NKC 8
#define PEK (V/NKC)      /* 4016 */
#define PEKW (PEK/8)     /* 502  */
#define NCBV (V/32)      /* 1004 */

// ---------------- device scratch ----------------
__device__ float g_x[BS*D];
__device__ float g_h[BS*D];
__device__ float g_q[BS*D];
__device__ float g_k[BS*D];
__device__ float g_v[BS*D];
__device__ float g_ao[BS*D];
__device__ float g_ff[BS*DFF];
__device__ float g_hs[BS*D];
__device__ float g_cK[L*BS*D];
__device__ float g_cV[L*BS*D];
__device__ float g_sK[L*B*MAX_ITER*D];
__device__ float g_sV[L*B*MAX_ITER*D];
__device__ float g_xt[B*D];
__device__ float g_qt[B*D];
__device__ float g_at[B*D];
__device__ float g_fft[B*DFF];
__device__ float g_bias[BS];
__device__ float g_part[NKC*B*D];
__device__ float g_psum[NCBV*4];
__device__ float g_pmax[NCBV*4];
__device__ int   g_pidx[NCBV*4];
__device__ unsigned g_barcnt;
__device__ unsigned g_barsense;

// ---------------- grid barrier ----------------
__device__ __forceinline__ void gridbar() {
    __syncthreads();
    if (threadIdx.x == 0) {
        __threadfence();
        unsigned cur = *(volatile unsigned*)&g_barsense;
        if (atomicAdd(&g_barcnt, 1u) == NB - 1u) {
            g_barcnt = 0u;
            __threadfence();
            *(volatile unsigned*)&g_barsense = cur + 1u;
        } else {
            while (*(volatile unsigned*)&g_barsense == cur) { __nanosleep(64); }
        }
        __threadfence();
    }
    __syncthreads();
}

// ---------------- encoder tiled GEMM phase ----------------
__device__ void gemm_phase(char* sb, const float* __restrict__ A,
                           const float* __restrict__ W, const float* res,
                           float* C, int M, int N, int K, int relu) {
    float* As = (float*)sb;
    float* Ws = (float*)(sb + 4096);
    int tid = threadIdx.x;
    int n = tid & 31;
    int mg = tid >> 5;
    int tM = M >> 5, tN = N >> 5;
    for (int t = blockIdx.x; t < tM * tN; t += NB) {
        int bm = (t / tN) << 5, bn = (t % tN) << 5;
        float a0=0.f,a1=0.f,a2=0.f,a3=0.f;
        for (int k0 = 0; k0 < K; k0 += 32) {
            {
                int m = (tid*4) >> 5, k = (tid*4) & 31;
                float4 av = *(const float4*)(A + (long)(bm+m)*K + k0 + k);
                As[(k+0)*32 + m] = av.x; As[(k+1)*32 + m] = av.y;
                As[(k+2)*32 + m] = av.z; As[(k+3)*32 + m] = av.w;
            }
#pragma unroll
            for (int i = 0; i < 4; i++) {
                int idx = tid + i*NT;
                int k = idx >> 5, nn = idx & 31;
                Ws[k*32 + nn] = W[(long)(k0+k)*N + bn + nn];
            }
            __syncthreads();
#pragma unroll
            for (int k = 0; k < 32; k++) {
                float w = Ws[k*32 + n];
                a0 += As[k*32 + mg*4+0]*w;
                a1 += As[k*32 + mg*4+1]*w;
                a2 += As[k*32 + mg*4+2]*w;
                a3 += As[k*32 + mg*4+3]*w;
            }
            __syncthreads();
        }
        float accs[4] = {a0,a1,a2,a3};
#pragma unroll
        for (int i = 0; i < 4; i++) {
            long m = bm + mg*4 + i;
            float vv = accs[i];
            if (res)  vv += res[m*N + bn + n];
            if (relu) vv = fmaxf(vv, 0.f);
            C[m*N + bn + n] = vv;
        }
    }
}

// ---------------- RMSNorm phase ----------------
__device__ void rms_phase(char* sb, const float* in, const float* w,
                          float* out, int rows) {
    float* red = (float*)sb;
    int tid = threadIdx.x;
    for (int r = blockIdx.x; r < rows; r += NB) {
        const float* x = in + (long)r * D;
        float s = 0.f;
        for (int i = tid; i < D; i += NT) { float v = x[i]; s += v*v; }
        red[tid] = s; __syncthreads();
        for (int o = 128; o; o >>= 1) {
            if (tid < o) red[tid] += red[tid+o];
            __syncthreads();
        }
        float inv = rsqrtf(red[0] / (float)D + 1e-6f);
        __syncthreads();
        for (int i = tid; i < D; i += NT)
            out[(long)r*D + i] = x[i] * inv * w[i];
        __syncthreads();
    }
}

// ---------------- encoder attention ----------------
__device__ void enc_attn_phase(char* sb) {
    float* Ks = (float*)sb;
    float* Ps = (float*)(sb + 16384);
    int tid = threadIdx.x;
    for (int t = blockIdx.x; t < B*H; t += NB) {
        int b = t / H, h = t % H;
        for (int i = tid; i < S*DH; i += NT) {
            int j = i / DH, d = i % DH;
            Ks[j*DH + d] = g_k[(long)(b*S + j)*D + h*DH + d];
        }
        __syncthreads();
        for (int i = tid; i < S*S; i += NT) {
            int s = i / S, j = i % S;
            const float* qr = g_q + (long)(b*S + s)*D + h*DH;
            float acc = 0.f;
#pragma unroll
            for (int d = 0; d < DH; d++) acc += qr[d] * Ks[j*DH + d];
            Ps[s*S + j] = acc * 0.125f + g_bias[b*S + j];
        }
        __syncthreads();
        if (tid < S) {
            int s = tid;
            float mx = -1e30f;
            for (int j = 0; j < S; j++) mx = fmaxf(mx, Ps[s*S+j]);
            float sum = 0.f;
            for (int j = 0; j < S; j++) { float e = expf(Ps[s*S+j]-mx); Ps[s*S+j]=e; sum+=e; }
            float r = 1.f / sum;
            for (int j = 0; j < S; j++) Ps[s*S+j] *= r;
        }
        __syncthreads();
        for (int i = tid; i < S*DH; i += NT) {
            int s = i / DH, d = i % DH;
            float acc = 0.f;
            for (int j = 0; j < S; j++)
                acc += Ps[s*S+j] * g_v[(long)(b*S + j)*D + h*DH + d];
            g_ao[(long)(b*S + s)*D + h*DH + d] = acc;
        }
        __syncthreads();
    }
}

// ---------------- decoder gemv machinery ----------------
__device__ void stage_x(char* sb, const float* x, const float* lnw, int K) {
    float* xs  = (float*)sb;
    float* red = (float*)(sb + 32768);
    int tid = threadIdx.x;
    if (lnw) {
        int base = tid * 8;
        int b = base >> 9;
        float vals[8];
        float s = 0.f;
#pragma unroll
        for (int j = 0; j < 8; j++) { vals[j] = x[base+j]; s += vals[j]*vals[j]; }
        red[tid] = s; __syncthreads();
        if (tid < 4) {
            float t = 0.f;
            for (int i = 0; i < 64; i++) t += red[tid*64 + i];
            red[1000 + tid] = rsqrtf(t / 512.0f + 1e-6f);
        }
        __syncthreads();
        float inv = red[1000 + b];
#pragma unroll
        for (int j = 0; j < 8; j++)
            xs[base+j] = vals[j] * inv * lnw[(base+j) & 511];
    } else {
        for (int i = tid; i < 4*K; i += NT) xs[i] = x[i];
    }
    __syncthreads();
}

__device__ __forceinline__ void gemv_one(char* sb, int K, int N,
        const float* __restrict__ W, int cb, float* outp, long ostride,
        const float* res, long rstride, int relu) {
    float* xs  = (float*)sb;
    float* red = (float*)(sb + 32768);
    int tid = threadIdx.x;
    int c = tid & 31, ws = tid >> 5;
    int Kc = K >> 3;
    int col = (cb << 5) + c;
    const float* Wp = W + (long)ws * Kc * N + col;
    const float* x0 = xs + ws * Kc;
    float a0=0.f,a1=0.f,a2=0.f,a3=0.f;
#pragma unroll 16
    for (int kk = 0; kk < Kc; kk++) {
        float w = Wp[(long)kk * N];
        a0 += x0[kk]       * w;
        a1 += x0[K + kk]   * w;
        a2 += x0[2*K + kk] * w;
        a3 += x0[3*K + kk] * w;
    }
    red[tid*4+0]=a0; red[tid*4+1]=a1; red[tid*4+2]=a2; red[tid*4+3]=a3;
    __syncthreads();
    if (tid < 128) {
        int cc = tid & 31, b = tid >> 5;
        float s = 0.f;
#pragma unroll
        for (int w8 = 0; w8 < 8; w8++) s += red[((w8<<5)+cc)*4 + b];
        int ocol = (cb << 5) + cc;
        if (res)  s += res[(long)b*rstride + ocol];
        if (relu) s = fmaxf(s, 0.f);
        outp[(long)b*ostride + ocol] = s;
    }
    __syncthreads();
}

__device__ void gemv_mat(char* sb, int K, int N, const float* W,
                         float* outp, long ostride, const float* res,
                         long rstride, int relu) {
    int ncb = N >> 5;
    for (int cb = blockIdx.x; cb < ncb; cb += NB)
        gemv_one(sb, K, N, W, cb, outp, ostride, res, rstride, relu);
}

__device__ void gemv3(char* sb, const float* W0, const float* W1, const float* W2,
                      float* o0, long os0, float* o1, long os1, float* o2, long os2) {
    int ncb = D >> 5;
    for (int t = blockIdx.x; t < 3*ncb; t += NB) {
        int m = t / ncb, cb = t % ncb;
        const float* W = (m==0) ? W0 : (m==1) ? W1 : W2;
        float* op      = (m==0) ? o0 : (m==1) ? o1 : o2;
        long os        = (m==0) ? os0 : (m==1) ? os1 : os2;
        gemv_one(sb, D, D, W, cb, op, os, 0, 0, 0);
    }
}

// ---------------- decoder attention ----------------
__device__ void dec_selfattn(char* sb, const float* kc, const float* vc, int len) {
    float* qsh = (float*)sb;
    float* p   = qsh + 64;
    int tid = threadIdx.x;
    for (int t = blockIdx.x; t < B*H; t += NB) {
        int b = t >> 3, h = t & 7;
        if (tid < 64) qsh[tid] = g_qt[b*D + h*DH + tid];
        __syncthreads();
        if (tid < len) {
            const float* kr = kc + (long)(b*MAX_ITER + tid)*D + h*DH;
            float acc = 0.f;
#pragma unroll
            for (int d = 0; d < DH; d++) acc += qsh[d]*kr[d];
            p[tid] = acc * 0.125f;
        }
        __syncthreads();
        if (tid == 0) {
            float mx = -1e30f;
            for (int j = 0; j < len; j++) mx = fmaxf(mx, p[j]);
            float sum = 0.f;
            for (int j = 0; j < len; j++) { float e = expf(p[j]-mx); p[j]=e; sum+=e; }
            float r = 1.f/sum;
            for (int j = 0; j < len; j++) p[j] *= r;
        }
        __syncthreads();
        if (tid < 64) {
            float acc = 0.f;
            for (int j = 0; j < len; j++)
                acc += p[j] * vc[(long)(b*MAX_ITER + j)*D + h*DH + tid];
            g_at[b*D + h*DH + tid] = acc;
        }
        __syncthreads();
    }
}

__device__ void dec_crossattn(char* sb, const float* kc, const float* vc) {
    float* qsh = (float*)sb;
    float* p   = qsh + 64;
    int tid = threadIdx.x;
    for (int t = blockIdx.x; t < B*H; t += NB) {
        int b = t >> 3, h = t & 7;
        if (tid < 64) qsh[tid] = g_qt[b*D + h*DH + tid];
        __syncthreads();
        if (tid < S) {
            const float* kr = kc + (long)(b*S + tid)*D + h*DH;
            float acc = 0.f;
#pragma unroll
            for (int d = 0; d < DH; d++) acc += qsh[d]*kr[d];
            p[tid] = acc * 0.125f + g_bias[b*S + tid];
        }
        __syncthreads();
        if (tid == 0) {
            float mx = -1e30f;
            for (int j = 0; j < S; j++) mx = fmaxf(mx, p[j]);
            float sum = 0.f;
            for (int j = 0; j < S; j++) { float e = expf(p[j]-mx); p[j]=e; sum+=e; }
            float r = 1.f/sum;
            for (int j = 0; j < S; j++) p[j] *= r;
        }
        __syncthreads();
        if (tid < 64) {
            float acc = 0.f;
            for (int j = 0; j < S; j++)
                acc += p[j] * vc[(long)(b*S + j)*D + h*DH + tid];
            g_at[b*D + h*DH + tid] = acc;
        }
        __syncthreads();
    }
}

// ---------------- phase A: lm_head + exp + partial sum/argmax ----------------
// Assumes stage_x(g_xt, dec_lnf) already done (hnorm in smem xs).
__device__ void lmhead_phase(char* sb, const float* __restrict__ lm,
                             float* out, int it) {
    float* xs  = (float*)sb;
    float* red = (float*)(sb + 32768);
    int tid = threadIdx.x;
    int c = tid & 31, ws = tid >> 5;
    for (int cb = blockIdx.x; cb < NCBV; cb += NB) {
        int col = (cb << 5) + c;
        const float* Wp = lm + (long)(ws * 64) * V + col;
        const float* x0 = xs + ws * 64;
        float a0=0.f,a1=0.f,a2=0.f,a3=0.f;
#pragma unroll 16
        for (int kk = 0; kk < 64; kk++) {
            float w = Wp[(long)kk * V];
            a0 += x0[kk]         * w;
            a1 += x0[D + kk]     * w;
            a2 += x0[2*D + kk]   * w;
            a3 += x0[3*D + kk]   * w;
        }
        red[tid*4+0]=a0; red[tid*4+1]=a1; red[tid*4+2]=a2; red[tid*4+3]=a3;
        __syncthreads();
        if (tid < 128) {
            int cc = tid & 31, b = tid >> 5;   // warp b handles batch b
            float s = 0.f;
#pragma unroll
            for (int w8 = 0; w8 < 8; w8++) s += red[((w8<<5)+cc)*4 + b];
            float e = expf(s);
            int gcol = (cb << 5) + cc;
            out[(long)(b*MAX_ITER + it)*V + gcol] = e;
            // warp reduce: sum, max (lowest index on tie)
            float m = e; int mi = gcol; float ss = e;
#pragma unroll
            for (int off = 16; off; off >>= 1) {
                float om = __shfl_xor_sync(0xffffffffu, m, off);
                int omi  = __shfl_xor_sync(0xffffffffu, mi, off);
                float os = __shfl_xor_sync(0xffffffffu, ss, off);
                ss += os;
                if (om > m || (om == m && omi < mi)) { m = om; mi = omi; }
            }
            if (cc == 0) {
                g_psum[cb*4 + b] = ss;
                g_pmax[cb*4 + b] = m;
                g_pidx[cb*4 + b] = mi;
            }
        }
        __syncthreads();
    }
}

// ---------------- phase B: e @ emb partials ----------------
__device__ void pe_partial(char* sb, const float* __restrict__ probs,
                           const float* __restrict__ emb, long rstride) {
    float* red = (float*)(sb + 32768);
    int tid = threadIdx.x;
    int c = tid & 31, ws = tid >> 5;
    for (int t = blockIdx.x; t < 16*NKC; t += NB) {
        int cb = t & 15, kc = t >> 4;
        int col = cb*32 + c;
        int k0 = kc*PEK + ws*PEKW;
        const float* ep = emb + (long)k0*D + col;
        const float* p0 = probs + k0;
        float a0=0.f,a1=0.f,a2=0.f,a3=0.f;
#pragma unroll 16
        for (int kk = 0; kk < PEKW; kk++) {
            float w = ep[(long)kk*D];
            a0 += p0[kk]             * w;
            a1 += p0[rstride   + kk] * w;
            a2 += p0[2*rstride + kk] * w;
            a3 += p0[3*rstride + kk] * w;
        }
        red[tid*4+0]=a0; red[tid*4+1]=a1; red[tid*4+2]=a2; red[tid*4+3]=a3;
        __syncthreads();
        if (tid < 128) {
            int cc = tid & 31, b = tid >> 5;
            float s = 0.f;
#pragma unroll
            for (int w8 = 0; w8 < 8; w8++) s += red[((w8<<5)+cc)*4 + b];
            g_part[((long)kc*B + b)*D + cb*32 + cc] = s;
        }
        __syncthreads();
    }
}

// ---------------- phase C: normalize + pred + next y ----------------
__device__ void finalize_phase(char* sb, float* out, int it, int do_pe) {
    int tid = threadIdx.x;
    float* red4 = (float*)(sb + 32768);   // 256*4 floats
    // 1. every block computes total sums over NCBV tasks
    float s0=0.f,s1=0.f,s2=0.f,s3=0.f;
    for (int i = tid; i < NCBV; i += NT) {
        float4 v = *(const float4*)(g_psum + i*4);
        s0 += v.x; s1 += v.y; s2 += v.z; s3 += v.w;
    }
    red4[tid*4+0]=s0; red4[tid*4+1]=s1; red4[tid*4+2]=s2; red4[tid*4+3]=s3;
    __syncthreads();
    for (int o = 128; o; o >>= 1) {
        if (tid < o) {
#pragma unroll
            for (int b = 0; b < 4; b++) red4[tid*4+b] += red4[(tid+o)*4+b];
        }
        __syncthreads();
    }
    float inv[4];
#pragma unroll
    for (int b = 0; b < 4; b++) inv[b] = 1.0f / red4[b];
    __syncthreads();
    // 2. blocks 0..3: global argmax with first-index tie break
    if (blockIdx.x < 4) {
        int b = blockIdx.x;
        float* msh = (float*)sb;           // reuse xs region
        int*   ish = (int*)(sb + 1024);
        float m = -1.0f; int mi = V;
        for (int i = tid; i < NCBV; i += NT) {
            float vm = g_pmax[i*4 + b]; int vi = g_pidx[i*4 + b];
            if (vm > m || (vm == m && vi < mi)) { m = vm; mi = vi; }
        }
        msh[tid] = m; ish[tid] = mi; __syncthreads();
        for (int o = 128; o; o >>= 1) {
            if (tid < o) {
                if (msh[tid+o] > msh[tid] ||
                    (msh[tid+o] == msh[tid] && ish[tid+o] < ish[tid])) {
                    msh[tid] = msh[tid+o]; ish[tid] = ish[tid+o];
                }
            }
            __syncthreads();
        }
        if (tid == 0)
            out[(long)B*MAX_ITER*V + b*MAX_ITER + it] = (ish[0] == 0) ? 1.0f : 0.0f;
    }
    // 3. scale out probs by 1/sum
#pragma unroll
    for (int b = 0; b < 4; b++) {
        float* pr = out + (long)(b*MAX_ITER + it)*V;
        float ib = inv[b];
        for (int i = blockIdx.x*NT + tid; i < V; i += NB*NT) pr[i] *= ib;
    }
    // 4. next y: g_xt = (sum_kc partials) / sum
    if (do_pe) {
        for (int i = blockIdx.x*NT + tid; i < B*D; i += NB*NT) {
            float s = 0.f;
#pragma unroll
            for (int kc = 0; kc < NKC; kc++) s += g_part[(long)kc*B*D + i];
            g_xt[i] = s * inv[i / D];
        }
    }
}

// ---------------- megakernel ----------------
__global__ void __launch_bounds__(NT, 1) mega(
    const int* ids, const float* mask, const float* emb,
    const float* enc_wq, const float* enc_wk, const float* enc_wv, const float* enc_wo,
    const float* enc_ln1, const float* enc_w1, const float* enc_w2,
    const float* enc_ln2, const float* enc_lnf,
    const float* dec_sq, const float* dec_sk, const float* dec_sv, const float* dec_so,
    const float* dec_ln1, const float* dec_cq, const float* dec_ck, const float* dec_cv,
    const float* dec_co, const float* dec_ln2, const float* dec_w1, const float* dec_w2,
    const float* dec_ln3, const float* dec_lnf, const float* lm_head, float* out)
{
    __shared__ __align__(16) float sbf[(32768 + 4096)/4];
    char* sb = (char*)sbf;
    int tid = threadIdx.x;

    // ---- init ----
    for (int i = blockIdx.x*NT + tid; i < BS*D; i += NB*NT) {
        int row = i / D, d = i % D;
        g_x[i] = emb[(long)ids[row]*D + d];
    }
    for (int i = blockIdx.x*NT + tid; i < BS; i += NB*NT)
        g_bias[i] = (1.0f - mask[i]) * NEGB;
    for (int i = blockIdx.x*NT + tid; i < B*D; i += NB*NT)
        g_xt[i] = emb[i % D];
    gridbar();

    // ---- encoder ----
    for (int l = 0; l < L; l++) {
        rms_phase(sb, g_x, enc_ln1 + l*D, g_h, BS); gridbar();
        gemm_phase(sb, g_h, enc_wq + (long)l*D*D, 0, g_q, BS, D, D, 0);
        gemm_phase(sb, g_h, enc_wk + (long)l*D*D, 0, g_k, BS, D, D, 0);
        gemm_phase(sb, g_h, enc_wv + (long)l*D*D, 0, g_v, BS, D, D, 0);
        gridbar();
        enc_attn_phase(sb); gridbar();
        gemm_phase(sb, g_ao, enc_wo + (long)l*D*D, g_x, g_x, BS, D, D, 0); gridbar();
        rms_phase(sb, g_x, enc_ln2 + l*D, g_h, BS); gridbar();
        gemm_phase(sb, g_h, enc_w1 + (long)l*D*DFF, 0, g_ff, BS, DFF, D, 1); gridbar();
        gemm_phase(sb, g_ff, enc_w2 + (long)l*DFF*D, g_x, g_x, BS, D, DFF, 0); gridbar();
    }
    rms_phase(sb, g_x, enc_lnf, g_hs, BS); gridbar();
    for (int l = 0; l < L; l++) {
        gemm_phase(sb, g_hs, dec_ck + (long)l*D*D, 0, g_cK + (long)l*BS*D, BS, D, D, 0);
        gemm_phase(sb, g_hs, dec_cv + (long)l*D*D, 0, g_cV + (long)l*BS*D, BS, D, D, 0);
    }
    gridbar();

    // ---- decoder ----
    for (int it = 0; it < MAX_ITER; it++) {
        int len = it + 1;
        for (int l = 0; l < L; l++) {
            float* kcb = g_sK + (long)l*B*MAX_ITER*D;
            float* vcb = g_sV + (long)l*B*MAX_ITER*D;
            stage_x(sb, g_xt, dec_ln1 + l*D, D);
            gemv3(sb, dec_sq + (long)l*D*D, dec_sk + (long)l*D*D, dec_sv + (long)l*D*D,
                  g_qt, D, kcb + (long)it*D, (long)MAX_ITER*D, vcb + (long)it*D, (long)MAX_ITER*D);
            gridbar();
            dec_selfattn(sb, kcb, vcb, len); gridbar();
            stage_x(sb, g_at, 0, D);
            gemv_mat(sb, D, D, dec_so + (long)l*D*D, g_xt, D, g_xt, D, 0); gridbar();
            stage_x(sb, g_xt, dec_ln2 + l*D, D);
            gemv_mat(sb, D, D, dec_cq + (long)l*D*D, g_qt, D, 0, 0, 0); gridbar();
            dec_crossattn(sb, g_cK + (long)l*BS*D, g_cV + (long)l*BS*D); gridbar();
            stage_x(sb, g_at, 0, D);
            gemv_mat(sb, D, D, dec_co + (long)l*D*D, g_xt, D, g_xt, D, 0); gridbar();
            stage_x(sb, g_xt, dec_ln3 + l*D, D);
            gemv_mat(sb, D, DFF, dec_w1 + (long)l*D*DFF, g_fft, DFF, 0, 0, 1); gridbar();
            stage_x(sb, g_fft, 0, DFF);
            gemv_mat(sb, DFF, D, dec_w2 + (long)l*DFF*D, g_xt, D, g_xt, D, 0); gridbar();
        }
        // phase A: lm_head + exp + partials
        stage_x(sb, g_xt, dec_lnf, D);
        lmhead_phase(sb, lm_head, out, it); gridbar();
        // phase B: e @ emb
        int do_pe = (it + 1 < MAX_ITER);
        if (do_pe) {
            pe_partial(sb, out + (long)it*V, emb, (long)MAX_ITER*V);
            gridbar();
        }
        // phase C: normalize + pred + next y
        finalize_phase(sb, out, it, do_pe); gridbar();
    }
}

// ---------------- host ----------------
extern "C" void kernel_launch(void* const* d_in, const int* in_sizes, int n_in,
                              void* d_out, int out_size) {
    mega<<<NB, NT>>>(
        (const int*)d_in[0], (const float*)d_in[1], (const float*)d_in[2],
        (const float*)d_in[3], (const float*)d_in[4], (const float*)d_in[5],
        (const float*)d_in[6], (const float*)d_in[7], (const float*)d_in[8],
        (const float*)d_in[9], (const float*)d_in[10], (const float*)d_in[11],
        (const float*)d_in[12], (const float*)d_in[13], (const float*)d_in[14],
        (const float*)d_in[15], (const float*)d_in[16], (const float*)d_in[17],
        (const float*)d_in[18], (const float*)d_in[19], (const float*)d_in[20],
        (const float*)d_in[21], (const float*)d_in[22], (const float*)d_in[23],
        (const float*)d_in[24], (const float*)d_in[25], (const float*)d_in[26],
        (float*)d_out);
}

// round 5
// speedup vs baseline: 11.6819x; 1.2949x over previous
#include <cuda_runtime.h>
#include <math.h>

#define B 4
#define S 64
#define D 512
#define H 8
#define DH 64
#define DFF 2048
#define L 2
#define V 32128
#define MAX_ITER 16
#define NEGB (-1e9f)
#define BS (B*S)
#define NB 148
#define NT 256
#define NCB128 (V/128)     /* 251 */
#define PE_KC 37           /* K-chunks for probs@emb: 4 cb x 37 = 148 tasks */
#define PE_BASE 868        /* 36*868 + 880 = 32128 */
#define PE_MAXL 880

// ---------------- device scratch ----------------
__device__ float g_x[BS*D];
__device__ float g_h[BS*D];
__device__ float g_q[BS*D];
__device__ float g_k[BS*D];
__device__ float g_v[BS*D];
__device__ float g_ao[BS*D];
__device__ float g_ff[BS*DFF];
__device__ float g_hs[BS*D];
__device__ float g_cK[L*BS*D];
__device__ float g_cV[L*BS*D];
__device__ float g_sK[L*B*MAX_ITER*D];
__device__ float g_sV[L*B*MAX_ITER*D];
__device__ float g_xt[B*D];
__device__ float g_qt[B*D];
__device__ float g_at[B*D];
__device__ float g_fft[B*DFF];
__device__ float g_bias[BS];
__device__ float g_part[PE_KC*B*D];
__device__ float g_psum[NCB128*4];
__device__ float g_pmax[NCB128*4];
__device__ int   g_pidx[NCB128*4];
__device__ unsigned g_barcnt;
__device__ unsigned g_barsense;

// ---------------- grid barrier ----------------
__device__ __forceinline__ void gridbar() {
    __syncthreads();
    if (threadIdx.x == 0) {
        __threadfence();
        unsigned cur = *(volatile unsigned*)&g_barsense;
        if (atomicAdd(&g_barcnt, 1u) == NB - 1u) {
            g_barcnt = 0u;
            __threadfence();
            *(volatile unsigned*)&g_barsense = cur + 1u;
        } else {
            while (*(volatile unsigned*)&g_barsense == cur) { __nanosleep(32); }
        }
        __threadfence();
    }
    __syncthreads();
}

// ---------------- encoder tiled GEMM phase ----------------
__device__ void gemm_phase(char* sb, const float* __restrict__ A,
                           const float* __restrict__ W, const float* res,
                           float* C, int M, int N, int K, int relu) {
    float* As = (float*)sb;
    float* Ws = (float*)(sb + 4096);
    int tid = threadIdx.x;
    int n = tid & 31;
    int mg = tid >> 5;
    int tM = M >> 5, tN = N >> 5;
    for (int t = blockIdx.x; t < tM * tN; t += NB) {
        int bm = (t / tN) << 5, bn = (t % tN) << 5;
        float a0=0.f,a1=0.f,a2=0.f,a3=0.f;
        for (int k0 = 0; k0 < K; k0 += 32) {
            {
                int m = (tid*4) >> 5, k = (tid*4) & 31;
                float4 av = *(const float4*)(A + (long)(bm+m)*K + k0 + k);
                As[(k+0)*32 + m] = av.x; As[(k+1)*32 + m] = av.y;
                As[(k+2)*32 + m] = av.z; As[(k+3)*32 + m] = av.w;
            }
            {
                int k = tid >> 3, n4 = (tid & 7) << 2;
                float4 wv = *(const float4*)(W + (long)(k0+k)*N + bn + n4);
                *(float4*)(Ws + k*32 + n4) = wv;
            }
            __syncthreads();
#pragma unroll
            for (int k = 0; k < 32; k++) {
                float w = Ws[k*32 + n];
                a0 += As[k*32 + mg*4+0]*w;
                a1 += As[k*32 + mg*4+1]*w;
                a2 += As[k*32 + mg*4+2]*w;
                a3 += As[k*32 + mg*4+3]*w;
            }
            __syncthreads();
        }
        float accs[4] = {a0,a1,a2,a3};
#pragma unroll
        for (int i = 0; i < 4; i++) {
            long m = bm + mg*4 + i;
            float vv = accs[i];
            if (res)  vv += res[m*N + bn + n];
            if (relu) vv = fmaxf(vv, 0.f);
            C[m*N + bn + n] = vv;
        }
    }
}

// ---------------- RMSNorm phase ----------------
__device__ void rms_phase(char* sb, const float* in, const float* w,
                          float* out, int rows) {
    float* red = (float*)sb;
    int tid = threadIdx.x;
    for (int r = blockIdx.x; r < rows; r += NB) {
        const float* x = in + (long)r * D;
        float s = 0.f;
        for (int i = tid; i < D; i += NT) { float v = x[i]; s += v*v; }
        red[tid] = s; __syncthreads();
        for (int o = 128; o; o >>= 1) {
            if (tid < o) red[tid] += red[tid+o];
            __syncthreads();
        }
        float inv = rsqrtf(red[0] / (float)D + 1e-6f);
        __syncthreads();
        for (int i = tid; i < D; i += NT)
            out[(long)r*D + i] = x[i] * inv * w[i];
        __syncthreads();
    }
}

// ---------------- encoder attention ----------------
__device__ void enc_attn_phase(char* sb) {
    float* Ks = (float*)sb;
    float* Ps = (float*)(sb + 16384);
    int tid = threadIdx.x;
    for (int t = blockIdx.x; t < B*H; t += NB) {
        int b = t / H, h = t % H;
        for (int i = tid; i < S*DH; i += NT) {
            int j = i / DH, d = i % DH;
            Ks[j*DH + d] = g_k[(long)(b*S + j)*D + h*DH + d];
        }
        __syncthreads();
        for (int i = tid; i < S*S; i += NT) {
            int s = i / S, j = i % S;
            const float* qr = g_q + (long)(b*S + s)*D + h*DH;
            float acc = 0.f;
#pragma unroll
            for (int d = 0; d < DH; d++) acc += qr[d] * Ks[j*DH + d];
            Ps[s*S + j] = acc * 0.125f + g_bias[b*S + j];
        }
        __syncthreads();
        if (tid < S) {
            int s = tid;
            float mx = -1e30f;
            for (int j = 0; j < S; j++) mx = fmaxf(mx, Ps[s*S+j]);
            float sum = 0.f;
            for (int j = 0; j < S; j++) { float e = expf(Ps[s*S+j]-mx); Ps[s*S+j]=e; sum+=e; }
            float r = 1.f / sum;
            for (int j = 0; j < S; j++) Ps[s*S+j] *= r;
        }
        __syncthreads();
        for (int i = tid; i < S*DH; i += NT) {
            int s = i / DH, d = i % DH;
            float acc = 0.f;
            for (int j = 0; j < S; j++)
                acc += Ps[s*S+j] * g_v[(long)(b*S + j)*D + h*DH + d];
            g_ao[(long)(b*S + s)*D + h*DH + d] = acc;
        }
        __syncthreads();
    }
}

// ---------------- decoder gemv machinery ----------------
__device__ void stage_x(char* sb, const float* x, const float* lnw, int K) {
    float* xs  = (float*)sb;
    float* red = (float*)(sb + 32768);
    int tid = threadIdx.x;
    if (lnw) {
        int base = tid * 8;
        int b = base >> 9;
        float vals[8];
        float s = 0.f;
#pragma unroll
        for (int j = 0; j < 8; j++) { vals[j] = x[base+j]; s += vals[j]*vals[j]; }
        red[tid] = s; __syncthreads();
        if (tid < 4) {
            float t = 0.f;
            for (int i = 0; i < 64; i++) t += red[tid*64 + i];
            red[1000 + tid] = rsqrtf(t / 512.0f + 1e-6f);
        }
        __syncthreads();
        float inv = red[1000 + b];
#pragma unroll
        for (int j = 0; j < 8; j++)
            xs[base+j] = vals[j] * inv * lnw[(base+j) & 511];
    } else {
        float4* xs4 = (float4*)xs;
        const float4* x4 = (const float4*)x;
        for (int i = tid; i < K; i += NT) xs4[i] = x4[i];   // K here = 4*Kdim/4
    }
    __syncthreads();
}

// one 32-col block of out[4,N] = xs[4,K] @ W[K,N]; 32-way K split, float4 loads
__device__ __forceinline__ void gemv_one(char* sb, int K, int N,
        const float* __restrict__ W, int cb, float* outp, long ostride,
        const float* res, long rstride, int relu) {
    const float* xs = (const float*)sb;
    float4* red4 = (float4*)(sb + 32768);
    int tid = threadIdx.x;
    int c = tid & 7, ws = tid >> 3;       // c: 4-col group, ws: K-slice 0..31
    int Kc = K >> 5;
    int col0 = (cb << 5) + (c << 2);
    const float* Wp = W + (long)(ws * Kc) * N + col0;
    const float* x0 = xs + ws * Kc;
    float4 a0 = {0,0,0,0}, a1 = a0, a2 = a0, a3 = a0;
#pragma unroll 8
    for (int kk = 0; kk < Kc; kk++) {
        float4 w = *(const float4*)(Wp + (long)kk * N);
        float x0v = x0[kk], x1v = x0[K+kk], x2v = x0[2*K+kk], x3v = x0[3*K+kk];
        a0.x += x0v*w.x; a0.y += x0v*w.y; a0.z += x0v*w.z; a0.w += x0v*w.w;
        a1.x += x1v*w.x; a1.y += x1v*w.y; a1.z += x1v*w.z; a1.w += x1v*w.w;
        a2.x += x2v*w.x; a2.y += x2v*w.y; a2.z += x2v*w.z; a2.w += x2v*w.w;
        a3.x += x3v*w.x; a3.y += x3v*w.y; a3.z += x3v*w.z; a3.w += x3v*w.w;
    }
    int base = (ws*8 + c)*4;
    red4[base+0] = a0; red4[base+1] = a1; red4[base+2] = a2; red4[base+3] = a3;
    __syncthreads();
    if (tid < 128) {
        int cc = tid & 31, b = tid >> 5;
        int cg = cc >> 2, j = cc & 3;
        const float* redf = (const float*)red4;
        float s = 0.f;
#pragma unroll
        for (int w32 = 0; w32 < 32; w32++)
            s += redf[((w32*8 + cg)*4 + b)*4 + j];
        int ocol = (cb << 5) + cc;
        if (res)  s += res[(long)b*rstride + ocol];
        if (relu) s = fmaxf(s, 0.f);
        outp[(long)b*ostride + ocol] = s;
    }
    __syncthreads();
}

__device__ void gemv_mat(char* sb, int K, int N, const float* W,
                         float* outp, long ostride, const float* res,
                         long rstride, int relu) {
    int ncb = N >> 5;
    for (int cb = blockIdx.x; cb < ncb; cb += NB)
        gemv_one(sb, K, N, W, cb, outp, ostride, res, rstride, relu);
}

__device__ void gemv3(char* sb, const float* W0, const float* W1, const float* W2,
                      float* o0, long os0, float* o1, long os1, float* o2, long os2) {
    int ncb = D >> 5;
    for (int t = blockIdx.x; t < 3*ncb; t += NB) {
        int m = t / ncb, cb = t % ncb;
        const float* W = (m==0) ? W0 : (m==1) ? W1 : W2;
        float* op      = (m==0) ? o0 : (m==1) ? o1 : o2;
        long os        = (m==0) ? os0 : (m==1) ? os1 : os2;
        gemv_one(sb, D, D, W, cb, op, os, 0, 0, 0);
    }
}

// ---------------- decoder attention ----------------
__device__ void dec_selfattn(char* sb, const float* kc, const float* vc, int len) {
    float* qsh = (float*)sb;
    float* p   = qsh + 64;
    int tid = threadIdx.x;
    for (int t = blockIdx.x; t < B*H; t += NB) {
        int b = t >> 3, h = t & 7;
        if (tid < 64) qsh[tid] = g_qt[b*D + h*DH + tid];
        __syncthreads();
        if (tid < len) {
            const float* kr = kc + (long)(b*MAX_ITER + tid)*D + h*DH;
            float acc = 0.f;
#pragma unroll
            for (int d = 0; d < DH; d++) acc += qsh[d]*kr[d];
            p[tid] = acc * 0.125f;
        }
        __syncthreads();
        if (tid == 0) {
            float mx = -1e30f;
            for (int j = 0; j < len; j++) mx = fmaxf(mx, p[j]);
            float sum = 0.f;
            for (int j = 0; j < len; j++) { float e = expf(p[j]-mx); p[j]=e; sum+=e; }
            float r = 1.f/sum;
            for (int j = 0; j < len; j++) p[j] *= r;
        }
        __syncthreads();
        if (tid < 64) {
            float acc = 0.f;
            for (int j = 0; j < len; j++)
                acc += p[j] * vc[(long)(b*MAX_ITER + j)*D + h*DH + tid];
            g_at[b*D + h*DH + tid] = acc;
        }
        __syncthreads();
    }
}

__device__ void dec_crossattn(char* sb, const float* kc, const float* vc) {
    float* qsh = (float*)sb;
    float* p   = qsh + 64;
    int tid = threadIdx.x;
    for (int t = blockIdx.x; t < B*H; t += NB) {
        int b = t >> 3, h = t & 7;
        if (tid < 64) qsh[tid] = g_qt[b*D + h*DH + tid];
        __syncthreads();
        if (tid < S) {
            const float* kr = kc + (long)(b*S + tid)*D + h*DH;
            float acc = 0.f;
#pragma unroll
            for (int d = 0; d < DH; d++) acc += qsh[d]*kr[d];
            p[tid] = acc * 0.125f + g_bias[b*S + tid];
        }
        __syncthreads();
        if (tid == 0) {
            float mx = -1e30f;
            for (int j = 0; j < S; j++) mx = fmaxf(mx, p[j]);
            float sum = 0.f;
            for (int j = 0; j < S; j++) { float e = expf(p[j]-mx); p[j]=e; sum+=e; }
            float r = 1.f/sum;
            for (int j = 0; j < S; j++) p[j] *= r;
        }
        __syncthreads();
        if (tid < 64) {
            float acc = 0.f;
            for (int j = 0; j < S; j++)
                acc += p[j] * vc[(long)(b*S + j)*D + h*DH + tid];
            g_at[b*D + h*DH + tid] = acc;
        }
        __syncthreads();
    }
}

// ---------------- phase A: lm_head (float4) + exp + partial sum/argmax -------
__device__ void lmhead_phase(char* sb, const float* __restrict__ lm,
                             float* out, int it) {
    const float* xs = (const float*)sb;
    float4* red4 = (float4*)(sb + 32768);
    int tid = threadIdx.x;
    int c = tid & 31, ws = tid >> 5;      // 128 cols (32 x float4), 8 K-slices
    for (int cb = blockIdx.x; cb < NCB128; cb += NB) {
        int col0 = cb*128 + c*4;
        const float* Wp = lm + (long)(ws * 64) * V + col0;
        const float* x0 = xs + ws * 64;
        float4 a0 = {0,0,0,0}, a1 = a0, a2 = a0, a3 = a0;
#pragma unroll 16
        for (int kk = 0; kk < 64; kk++) {
            float4 w = *(const float4*)(Wp + (long)kk * V);
            float x0v = x0[kk], x1v = x0[D+kk], x2v = x0[2*D+kk], x3v = x0[3*D+kk];
            a0.x += x0v*w.x; a0.y += x0v*w.y; a0.z += x0v*w.z; a0.w += x0v*w.w;
            a1.x += x1v*w.x; a1.y += x1v*w.y; a1.z += x1v*w.z; a1.w += x1v*w.w;
            a2.x += x2v*w.x; a2.y += x2v*w.y; a2.z += x2v*w.z; a2.w += x2v*w.w;
            a3.x += x3v*w.x; a3.y += x3v*w.y; a3.z += x3v*w.z; a3.w += x3v*w.w;
        }
        int base = (ws*32 + c)*4;
        red4[base+0] = a0; red4[base+1] = a1; red4[base+2] = a2; red4[base+3] = a3;
        __syncthreads();
        if (tid < 128) {
            int cc = tid & 31, b = tid >> 5;   // warp b = batch b
            float4 s = {0,0,0,0};
#pragma unroll
            for (int w8 = 0; w8 < 8; w8++) {
                float4 v = red4[(w8*32 + cc)*4 + b];
                s.x += v.x; s.y += v.y; s.z += v.z; s.w += v.w;
            }
            float4 e;
            e.x = expf(s.x); e.y = expf(s.y); e.z = expf(s.z); e.w = expf(s.w);
            int gcol = cb*128 + cc*4;
            *(float4*)(out + (long)(b*MAX_ITER + it)*V + gcol) = e;
            float ssum = e.x + e.y + e.z + e.w;
            float m = e.x; int mi = gcol;
            if (e.y > m) { m = e.y; mi = gcol+1; }
            if (e.z > m) { m = e.z; mi = gcol+2; }
            if (e.w > m) { m = e.w; mi = gcol+3; }
#pragma unroll
            for (int off = 16; off; off >>= 1) {
                float om = __shfl_xor_sync(0xffffffffu, m, off);
                int omi  = __shfl_xor_sync(0xffffffffu, mi, off);
                float os = __shfl_xor_sync(0xffffffffu, ssum, off);
                ssum += os;
                if (om > m || (om == m && omi < mi)) { m = om; mi = omi; }
            }
            if (cc == 0) {
                g_psum[cb*4 + b] = ssum;
                g_pmax[cb*4 + b] = m;
                g_pidx[cb*4 + b] = mi;
            }
        }
        __syncthreads();
    }
}

// ---------------- phase B: e @ emb partials (float4, probs staged) ----------
__device__ void pe_partial(char* sb, const float* __restrict__ probs,
                           const float* __restrict__ emb, long rstride) {
    float* ps = (float*)sb;                  // [4][PE_MAXL]
    float4* red4 = (float4*)(sb + 32768);
    int tid = threadIdx.x;
    int c = tid & 31, ws = tid >> 5;
    int t = blockIdx.x;                      // exactly 148 tasks, 1 per block
    int cb = t & 3, kc = t >> 2;
    int len = (kc < PE_KC-1) ? PE_BASE : PE_MAXL;
    int k0 = kc * PE_BASE;
    // stage probs chunk
    for (int i = tid; i < 4*len; i += NT) {
        int r = i / len, kk = i % len;
        ps[r*PE_MAXL + kk] = probs[(long)r*rstride + k0 + kk];
    }
    __syncthreads();
    int sl = (len + 7) >> 3;
    int s0 = ws * sl; int s1 = s0 + sl; if (s1 > len) s1 = len;
    int col0 = cb*128 + c*4;
    float4 a0 = {0,0,0,0}, a1 = a0, a2 = a0, a3 = a0;
#pragma unroll 8
    for (int kk = s0; kk < s1; kk++) {
        float4 w = *(const float4*)(emb + (long)(k0 + kk)*D + col0);
        float e0 = ps[kk], e1 = ps[PE_MAXL+kk], e2 = ps[2*PE_MAXL+kk], e3 = ps[3*PE_MAXL+kk];
        a0.x += e0*w.x; a0.y += e0*w.y; a0.z += e0*w.z; a0.w += e0*w.w;
        a1.x += e1*w.x; a1.y += e1*w.y; a1.z += e1*w.z; a1.w += e1*w.w;
        a2.x += e2*w.x; a2.y += e2*w.y; a2.z += e2*w.z; a2.w += e2*w.w;
        a3.x += e3*w.x; a3.y += e3*w.y; a3.z += e3*w.z; a3.w += e3*w.w;
    }
    int base = (ws*32 + c)*4;
    red4[base+0] = a0; red4[base+1] = a1; red4[base+2] = a2; red4[base+3] = a3;
    __syncthreads();
    if (tid < 128) {
        int cc = tid & 31, b = tid >> 5;
        float4 s = {0,0,0,0};
#pragma unroll
        for (int w8 = 0; w8 < 8; w8++) {
            float4 v = red4[(w8*32 + cc)*4 + b];
            s.x += v.x; s.y += v.y; s.z += v.z; s.w += v.w;
        }
        *(float4*)(g_part + ((long)kc*B + b)*D + cb*128 + cc*4) = s;
    }
    __syncthreads();
}

// ---------------- phase C: normalize + pred + next y ----------------
__device__ void finalize_phase(char* sb, float* out, int it, int do_pe) {
    int tid = threadIdx.x;
    float* red4 = (float*)(sb + 32768);
    float s0=0.f,s1=0.f,s2=0.f,s3=0.f;
    for (int i = tid; i < NCB128; i += NT) {
        float4 v = *(const float4*)(g_psum + i*4);
        s0 += v.x; s1 += v.y; s2 += v.z; s3 += v.w;
    }
    red4[tid*4+0]=s0; red4[tid*4+1]=s1; red4[tid*4+2]=s2; red4[tid*4+3]=s3;
    __syncthreads();
    for (int o = 128; o; o >>= 1) {
        if (tid < o) {
#pragma unroll
            for (int b = 0; b < 4; b++) red4[tid*4+b] += red4[(tid+o)*4+b];
        }
        __syncthreads();
    }
    float inv[4];
#pragma unroll
    for (int b = 0; b < 4; b++) inv[b] = 1.0f / red4[b];
    __syncthreads();
    if (blockIdx.x < 4) {
        int b = blockIdx.x;
        float* msh = (float*)sb;
        int*   ish = (int*)(sb + 1024);
        float m = -1.0f; int mi = V;
        for (int i = tid; i < NCB128; i += NT) {
            float vm = g_pmax[i*4 + b]; int vi = g_pidx[i*4 + b];
            if (vm > m || (vm == m && vi < mi)) { m = vm; mi = vi; }
        }
        msh[tid] = m; ish[tid] = mi; __syncthreads();
        for (int o = 128; o; o >>= 1) {
            if (tid < o) {
                if (msh[tid+o] > msh[tid] ||
                    (msh[tid+o] == msh[tid] && ish[tid+o] < ish[tid])) {
                    msh[tid] = msh[tid+o]; ish[tid] = ish[tid+o];
                }
            }
            __syncthreads();
        }
        if (tid == 0)
            out[(long)B*MAX_ITER*V + b*MAX_ITER + it] = (ish[0] == 0) ? 1.0f : 0.0f;
    }
#pragma unroll
    for (int b = 0; b < 4; b++) {
        float4* pr = (float4*)(out + (long)(b*MAX_ITER + it)*V);
        float ib = inv[b];
        for (int i = blockIdx.x*NT + tid; i < V/4; i += NB*NT) {
            float4 v = pr[i];
            v.x *= ib; v.y *= ib; v.z *= ib; v.w *= ib;
            pr[i] = v;
        }
    }
    if (do_pe) {
        for (int i = blockIdx.x*NT + tid; i < B*D; i += NB*NT) {
            float s = 0.f;
#pragma unroll
            for (int kc = 0; kc < PE_KC; kc++) s += g_part[(long)kc*B*D + i];
            g_xt[i] = s * inv[i / D];
        }
    }
}

// ---------------- megakernel ----------------
__global__ void __launch_bounds__(NT, 1) mega(
    const int* ids, const float* mask, const float* emb,
    const float* enc_wq, const float* enc_wk, const float* enc_wv, const float* enc_wo,
    const float* enc_ln1, const float* enc_w1, const float* enc_w2,
    const float* enc_ln2, const float* enc_lnf,
    const float* dec_sq, const float* dec_sk, const float* dec_sv, const float* dec_so,
    const float* dec_ln1, const float* dec_cq, const float* dec_ck, const float* dec_cv,
    const float* dec_co, const float* dec_ln2, const float* dec_w1, const float* dec_w2,
    const float* dec_ln3, const float* dec_lnf, const float* lm_head, float* out)
{
    __shared__ __align__(16) float sbf[12288];   // 48KB: xs 32KB + red 16KB
    char* sb = (char*)sbf;
    int tid = threadIdx.x;

    // ---- init ----
    for (int i = blockIdx.x*NT + tid; i < BS*D; i += NB*NT) {
        int row = i / D, d = i % D;
        g_x[i] = emb[(long)ids[row]*D + d];
    }
    for (int i = blockIdx.x*NT + tid; i < BS; i += NB*NT)
        g_bias[i] = (1.0f - mask[i]) * NEGB;
    for (int i = blockIdx.x*NT + tid; i < B*D; i += NB*NT)
        g_xt[i] = emb[i % D];
    gridbar();

    // ---- encoder ----
    for (int l = 0; l < L; l++) {
        rms_phase(sb, g_x, enc_ln1 + l*D, g_h, BS); gridbar();
        gemm_phase(sb, g_h, enc_wq + (long)l*D*D, 0, g_q, BS, D, D, 0);
        gemm_phase(sb, g_h, enc_wk + (long)l*D*D, 0, g_k, BS, D, D, 0);
        gemm_phase(sb, g_h, enc_wv + (long)l*D*D, 0, g_v, BS, D, D, 0);
        gridbar();
        enc_attn_phase(sb); gridbar();
        gemm_phase(sb, g_ao, enc_wo + (long)l*D*D, g_x, g_x, BS, D, D, 0); gridbar();
        rms_phase(sb, g_x, enc_ln2 + l*D, g_h, BS); gridbar();
        gemm_phase(sb, g_h, enc_w1 + (long)l*D*DFF, 0, g_ff, BS, DFF, D, 1); gridbar();
        gemm_phase(sb, g_ff, enc_w2 + (long)l*DFF*D, g_x, g_x, BS, D, DFF, 0); gridbar();
    }
    rms_phase(sb, g_x, enc_lnf, g_hs, BS); gridbar();
    for (int l = 0; l < L; l++) {
        gemm_phase(sb, g_hs, dec_ck + (long)l*D*D, 0, g_cK + (long)l*BS*D, BS, D, D, 0);
        gemm_phase(sb, g_hs, dec_cv + (long)l*D*D, 0, g_cV + (long)l*BS*D, BS, D, D, 0);
    }
    gridbar();

    // ---- decoder ----
    for (int it = 0; it < MAX_ITER; it++) {
        int len = it + 1;
        for (int l = 0; l < L; l++) {
            float* kcb = g_sK + (long)l*B*MAX_ITER*D;
            float* vcb = g_sV + (long)l*B*MAX_ITER*D;
            stage_x(sb, g_xt, dec_ln1 + l*D, D);
            gemv3(sb, dec_sq + (long)l*D*D, dec_sk + (long)l*D*D, dec_sv + (long)l*D*D,
                  g_qt, D, kcb + (long)it*D, (long)MAX_ITER*D, vcb + (long)it*D, (long)MAX_ITER*D);
            gridbar();
            dec_selfattn(sb, kcb, vcb, len); gridbar();
            stage_x(sb, g_at, 0, D);
            gemv_mat(sb, D, D, dec_so + (long)l*D*D, g_xt, D, g_xt, D, 0); gridbar();
            stage_x(sb, g_xt, dec_ln2 + l*D, D);
            gemv_mat(sb, D, D, dec_cq + (long)l*D*D, g_qt, D, 0, 0, 0); gridbar();
            dec_crossattn(sb, g_cK + (long)l*BS*D, g_cV + (long)l*BS*D); gridbar();
            stage_x(sb, g_at, 0, D);
            gemv_mat(sb, D, D, dec_co + (long)l*D*D, g_xt, D, g_xt, D, 0); gridbar();
            stage_x(sb, g_xt, dec_ln3 + l*D, D);
            gemv_mat(sb, D, DFF, dec_w1 + (long)l*D*DFF, g_fft, DFF, 0, 0, 1); gridbar();
            stage_x(sb, g_fft, 0, DFF);
            gemv_mat(sb, DFF, D, dec_w2 + (long)l*DFF*D, g_xt, D, g_xt, D, 0); gridbar();
        }
        stage_x(sb, g_xt, dec_lnf, D);
        lmhead_phase(sb, lm_head, out, it); gridbar();
        int do_pe = (it + 1 < MAX_ITER);
        if (do_pe) {
            pe_partial(sb, out + (long)it*V, emb, (long)MAX_ITER*V);
            gridbar();
        }
        finalize_phase(sb, out, it, do_pe); gridbar();
    }
}

// ---------------- host ----------------
extern "C" void kernel_launch(void* const* d_in, const int* in_sizes, int n_in,
                              void* d_out, int out_size) {
    mega<<<NB, NT>>>(
        (const int*)d_in[0], (const float*)d_in[1], (const float*)d_in[2],
        (const float*)d_in[3], (const float*)d_in[4], (const float*)d_in[5],
        (const float*)d_in[6], (const float*)d_in[7], (const float*)d_in[8],
        (const float*)d_in[9], (const float*)d_in[10], (const float*)d_in[11],
        (const float*)d_in[12], (const float*)d_in[13], (const float*)d_in[14],
        (const float*)d_in[15], (const float*)d_in[16], (const float*)d_in[17],
        (const float*)d_in[18], (const float*)d_in[19], (const float*)d_in[20],
        (const float*)d_in[21], (const float*)d_in[22], (const float*)d_in[23],
        (const float*)d_in[24], (const float*)d_in[25], (const float*)d_in[26],
        (float*)d_out);
}

// round 7
// speedup vs baseline: 11.8606x; 1.0153x over previous
#include <cuda_runtime.h>
#include <math.h>

#define B 4
#define S 64
#define D 512
#define H 8
#define DH 64
#define DFF 2048
#define L 2
#define V 32128
#define MAX_ITER 16
#define NEGB (-1e9f)
#define BS (B*S)
#define NB 148
#define NT 256
#define NCB128 (V/128)     /* 251 */
#define PE_KC 37
#define PE_BASE 868
#define PE_MAXL 880

// ---------------- device scratch ----------------
__device__ float g_x[BS*D];
__device__ float g_h[BS*D];
__device__ float g_q[BS*D];
__device__ float g_k[BS*D];
__device__ float g_v[BS*D];
__device__ float g_ao[BS*D];
__device__ float g_ff[BS*DFF];
__device__ float g_hs[BS*D];
__device__ float g_cK[L*BS*D];
__device__ float g_cV[L*BS*D];
__device__ float g_sK[L*B*MAX_ITER*D];
__device__ float g_sV[L*B*MAX_ITER*D];
__device__ float g_X0[B*D];
__device__ float g_X1[B*D];
__device__ float g_sopart[B*H*D];
__device__ float g_copart[B*H*D];
__device__ float g_fft[B*DFF];
__device__ float g_bias[BS];
__device__ float g_part[PE_KC*B*D];
__device__ float g_psum[NCB128*4];
__device__ float g_pmax[NCB128*4];
__device__ int   g_pidx[NCB128*4];
__device__ float g_inv[MAX_ITER*4];
__device__ int   g_best[MAX_ITER*4];
__device__ unsigned g_barcnt;
__device__ unsigned g_barsense;

// ---------------- grid barrier ----------------
__device__ __forceinline__ void gridbar() {
    __syncthreads();
    if (threadIdx.x == 0) {
        __threadfence();
        unsigned cur = *(volatile unsigned*)&g_barsense;
        if (atomicAdd(&g_barcnt, 1u) == NB - 1u) {
            g_barcnt = 0u;
            __threadfence();
            *(volatile unsigned*)&g_barsense = cur + 1u;
        } else {
            while (*(volatile unsigned*)&g_barsense == cur) { __nanosleep(32); }
        }
        __threadfence();
    }
    __syncthreads();
}

// ---------------- encoder tiled GEMM phase (unchanged) ----------------
__device__ void gemm_phase(char* sb, const float* __restrict__ A,
                           const float* __restrict__ W, const float* res,
                           float* C, int M, int N, int K, int relu) {
    float* As = (float*)sb;
    float* Ws = (float*)(sb + 4096);
    int tid = threadIdx.x;
    int n = tid & 31;
    int mg = tid >> 5;
    int tM = M >> 5, tN = N >> 5;
    for (int t = blockIdx.x; t < tM * tN; t += NB) {
        int bm = (t / tN) << 5, bn = (t % tN) << 5;
        float a0=0.f,a1=0.f,a2=0.f,a3=0.f;
        for (int k0 = 0; k0 < K; k0 += 32) {
            {
                int m = (tid*4) >> 5, k = (tid*4) & 31;
                float4 av = *(const float4*)(A + (long)(bm+m)*K + k0 + k);
                As[(k+0)*32 + m] = av.x; As[(k+1)*32 + m] = av.y;
                As[(k+2)*32 + m] = av.z; As[(k+3)*32 + m] = av.w;
            }
            {
                int k = tid >> 3, n4 = (tid & 7) << 2;
                float4 wv = *(const float4*)(W + (long)(k0+k)*N + bn + n4);
                *(float4*)(Ws + k*32 + n4) = wv;
            }
            __syncthreads();
#pragma unroll
            for (int k = 0; k < 32; k++) {
                float w = Ws[k*32 + n];
                a0 += As[k*32 + mg*4+0]*w;
                a1 += As[k*32 + mg*4+1]*w;
                a2 += As[k*32 + mg*4+2]*w;
                a3 += As[k*32 + mg*4+3]*w;
            }
            __syncthreads();
        }
        float accs[4] = {a0,a1,a2,a3};
#pragma unroll
        for (int i = 0; i < 4; i++) {
            long m = bm + mg*4 + i;
            float vv = accs[i];
            if (res)  vv += res[m*N + bn + n];
            if (relu) vv = fmaxf(vv, 0.f);
            C[m*N + bn + n] = vv;
        }
    }
}

// ---------------- RMSNorm phase (encoder rows) ----------------
__device__ void rms_phase(char* sb, const float* in, const float* w,
                          float* out, int rows) {
    float* red = (float*)sb;
    int tid = threadIdx.x;
    for (int r = blockIdx.x; r < rows; r += NB) {
        const float* x = in + (long)r * D;
        float s = 0.f;
        for (int i = tid; i < D; i += NT) { float v = x[i]; s += v*v; }
        red[tid] = s; __syncthreads();
        for (int o = 128; o; o >>= 1) {
            if (tid < o) red[tid] += red[tid+o];
            __syncthreads();
        }
        float inv = rsqrtf(red[0] / (float)D + 1e-6f);
        __syncthreads();
        for (int i = tid; i < D; i += NT)
            out[(long)r*D + i] = x[i] * inv * w[i];
        __syncthreads();
    }
}

// ---------------- encoder attention (unchanged) ----------------
__device__ void enc_attn_phase(char* sb) {
    float* Ks = (float*)sb;
    float* Ps = (float*)(sb + 16384);
    int tid = threadIdx.x;
    for (int t = blockIdx.x; t < B*H; t += NB) {
        int b = t / H, h = t % H;
        for (int i = tid; i < S*DH; i += NT) {
            int j = i / DH, d = i % DH;
            Ks[j*DH + d] = g_k[(long)(b*S + j)*D + h*DH + d];
        }
        __syncthreads();
        for (int i = tid; i < S*S; i += NT) {
            int s = i / S, j = i % S;
            const float* qr = g_q + (long)(b*S + s)*D + h*DH;
            float acc = 0.f;
#pragma unroll
            for (int d = 0; d < DH; d++) acc += qr[d] * Ks[j*DH + d];
            Ps[s*S + j] = acc * 0.125f + g_bias[b*S + j];
        }
        __syncthreads();
        if (tid < S) {
            int s = tid;
            float mx = -1e30f;
            for (int j = 0; j < S; j++) mx = fmaxf(mx, Ps[s*S+j]);
            float sum = 0.f;
            for (int j = 0; j < S; j++) { float e = expf(Ps[s*S+j]-mx); Ps[s*S+j]=e; sum+=e; }
            float r = 1.f / sum;
            for (int j = 0; j < S; j++) Ps[s*S+j] *= r;
        }
        __syncthreads();
        for (int i = tid; i < S*DH; i += NT) {
            int s = i / DH, d = i % DH;
            float acc = 0.f;
            for (int j = 0; j < S; j++)
                acc += Ps[s*S+j] * g_v[(long)(b*S + j)*D + h*DH + d];
            g_ao[(long)(b*S + s)*D + h*DH + d] = acc;
        }
        __syncthreads();
    }
}

// ---------------- decoder stage: xs = rms(X + sum(parts), lnw) ----------------
__device__ void stage_rms(char* sb, const float* X, const float* lnw,
                          const float* part1, const float* part2) {
    float* xs  = (float*)sb;
    float* red = (float*)(sb + 32768);
    int tid = threadIdx.x;
    int base = tid * 8;          // 0..2047
    int b = base >> 9;
    int d0 = base & 511;
    float vals[8];
#pragma unroll
    for (int j2 = 0; j2 < 2; j2++) {
        float4 acc = *(const float4*)(X + base + j2*4);
        if (part1) {
#pragma unroll
            for (int h = 0; h < 8; h++) {
                float4 p = *(const float4*)(part1 + (long)(b*8+h)*D + d0 + j2*4);
                acc.x += p.x; acc.y += p.y; acc.z += p.z; acc.w += p.w;
            }
        }
        if (part2) {
#pragma unroll
            for (int h = 0; h < 8; h++) {
                float4 p = *(const float4*)(part2 + (long)(b*8+h)*D + d0 + j2*4);
                acc.x += p.x; acc.y += p.y; acc.z += p.z; acc.w += p.w;
            }
        }
        vals[j2*4+0]=acc.x; vals[j2*4+1]=acc.y; vals[j2*4+2]=acc.z; vals[j2*4+3]=acc.w;
    }
    float s = 0.f;
#pragma unroll
    for (int j = 0; j < 8; j++) s += vals[j]*vals[j];
    red[tid] = s; __syncthreads();
    if (tid < 4) {
        float t = 0.f;
        for (int i = 0; i < 64; i++) t += red[tid*64 + i];
        red[1000 + tid] = rsqrtf(t / 512.0f + 1e-6f);
    }
    __syncthreads();
    float inv = red[1000 + b];
#pragma unroll
    for (int j = 0; j < 8; j++)
        xs[base+j] = vals[j] * inv * lnw[d0 + j];
    __syncthreads();
}

// stage fft into xs (4 x 2048)
__device__ void stage_fft(char* sb) {
    float4* xs4 = (float4*)sb;
    const float4* f4 = (const float4*)g_fft;
    int tid = threadIdx.x;
    for (int i = tid; i < (4*DFF)/4; i += NT) xs4[i] = f4[i];
    __syncthreads();
}

// ---------------- generic 32-col gemv (used for w1) ----------------
__device__ __forceinline__ void gemv_one(char* sb, int K, int N,
        const float* __restrict__ W, int cb, float* outp, long ostride,
        const float* res, long rstride, int relu) {
    const float* xs = (const float*)sb;
    float4* red4 = (float4*)(sb + 32768);
    int tid = threadIdx.x;
    int c = tid & 7, ws = tid >> 3;
    int Kc = K >> 5;
    int col0 = (cb << 5) + (c << 2);
    const float* Wp = W + (long)(ws * Kc) * N + col0;
    const float* x0 = xs + ws * Kc;
    float4 a0 = {0,0,0,0}, a1 = a0, a2 = a0, a3 = a0;
#pragma unroll 8
    for (int kk = 0; kk < Kc; kk++) {
        float4 w = *(const float4*)(Wp + (long)kk * N);
        float x0v = x0[kk], x1v = x0[K+kk], x2v = x0[2*K+kk], x3v = x0[3*K+kk];
        a0.x += x0v*w.x; a0.y += x0v*w.y; a0.z += x0v*w.z; a0.w += x0v*w.w;
        a1.x += x1v*w.x; a1.y += x1v*w.y; a1.z += x1v*w.z; a1.w += x1v*w.w;
        a2.x += x2v*w.x; a2.y += x2v*w.y; a2.z += x2v*w.z; a2.w += x2v*w.w;
        a3.x += x3v*w.x; a3.y += x3v*w.y; a3.z += x3v*w.z; a3.w += x3v*w.w;
    }
    int base = (ws*8 + c)*4;
    red4[base+0] = a0; red4[base+1] = a1; red4[base+2] = a2; red4[base+3] = a3;
    __syncthreads();
    if (tid < 128) {
        int cc = tid & 31, b = tid >> 5;
        int cg = cc >> 2, j = cc & 3;
        const float* redf = (const float*)red4;
        float s = 0.f;
#pragma unroll
        for (int w32 = 0; w32 < 32; w32++)
            s += redf[((w32*8 + cg)*4 + b)*4 + j];
        int ocol = (cb << 5) + cc;
        if (res)  s += res[(long)b*rstride + ocol];
        if (relu) s = fmaxf(s, 0.f);
        outp[(long)b*ostride + ocol] = s;
    }
    __syncthreads();
}

__device__ void gemv_mat(char* sb, int K, int N, const float* W,
                         float* outp, long ostride, int relu) {
    int ncb = N >> 5;
    for (int cb = blockIdx.x; cb < ncb; cb += NB)
        gemv_one(sb, K, N, W, cb, outp, ostride, 0, 0, relu);
}

// ---------------- w2 gemv with residual-from-partials (K=DFF) --------------
__device__ void gemv_w2(char* sb, const float* __restrict__ W,
                        const float* Xin, float* Xout) {
    const float* xs = (const float*)sb;
    float4* red4 = (float4*)(sb + 32768);
    int tid = threadIdx.x;
    int cb = blockIdx.x;     // < 16
    int c = tid & 7, ws = tid >> 3;
    int Kc = DFF >> 5;       // 64
    int col0 = (cb << 5) + (c << 2);
    const float* Wp = W + (long)(ws * Kc) * D + col0;
    const float* x0 = xs + ws * Kc;
    float4 a0 = {0,0,0,0}, a1 = a0, a2 = a0, a3 = a0;
#pragma unroll 8
    for (int kk = 0; kk < Kc; kk++) {
        float4 w = *(const float4*)(Wp + (long)kk * D);
        float x0v = x0[kk], x1v = x0[DFF+kk], x2v = x0[2*DFF+kk], x3v = x0[3*DFF+kk];
        a0.x += x0v*w.x; a0.y += x0v*w.y; a0.z += x0v*w.z; a0.w += x0v*w.w;
        a1.x += x1v*w.x; a1.y += x1v*w.y; a1.z += x1v*w.z; a1.w += x1v*w.w;
        a2.x += x2v*w.x; a2.y += x2v*w.y; a2.z += x2v*w.z; a2.w += x2v*w.w;
        a3.x += x3v*w.x; a3.y += x3v*w.y; a3.z += x3v*w.z; a3.w += x3v*w.w;
    }
    int base = (ws*8 + c)*4;
    red4[base+0] = a0; red4[base+1] = a1; red4[base+2] = a2; red4[base+3] = a3;
    __syncthreads();
    if (tid < 128) {
        int cc = tid & 31, b = tid >> 5;
        int cg = cc >> 2, j = cc & 3;
        const float* redf = (const float*)red4;
        float s = 0.f;
#pragma unroll
        for (int w32 = 0; w32 < 32; w32++)
            s += redf[((w32*8 + cg)*4 + b)*4 + j];
        int ocol = (cb << 5) + cc;
        float r = Xin[(long)b*D + ocol];
#pragma unroll
        for (int h = 0; h < 8; h++) {
            r += g_sopart[(long)(b*8+h)*D + ocol];
            r += g_copart[(long)(b*8+h)*D + ocol];
        }
        Xout[(long)b*D + ocol] = r + s;
    }
    __syncthreads();
}

// ---------------- fused self-attention block (per b,h) ----------------
__device__ void fused_self(char* sb, int it, int len,
                           const float* sq, const float* sk, const float* sv,
                           const float* so, float* kcb, float* vcb) {
    int t = blockIdx.x;
    if (t >= 32) return;
    int b = t >> 3, h = t & 7;
    const float* xs = (const float*)sb;
    float* scr = (float*)(sb + 32768);
    float* qv  = scr;          // 64
    float* kv  = qv + 64;      // 64
    float* vv  = kv + 64;      // 64
    float* csm = vv + 64;      // 64
    float* p   = csm + 64;     // 32
    float* red = p + 32;       // 1024
    int tid = threadIdx.x;
    const float* xb = xs + b * 512;
    int c4 = tid & 15, ws = tid >> 4;
    const float* mats[3] = {sq, sk, sv};
    float* outs[3] = {qv, kv, vv};
#pragma unroll
    for (int m = 0; m < 3; m++) {
        const float* W = mats[m] + (long)(ws*32)*D + h*64 + c4*4;
        const float* x0 = xb + ws*32;
        float4 a = {0,0,0,0};
#pragma unroll
        for (int kk = 0; kk < 32; kk++) {
            float4 w = *(const float4*)(W + (long)kk*D);
            float x = x0[kk];
            a.x += x*w.x; a.y += x*w.y; a.z += x*w.z; a.w += x*w.w;
        }
        *(float4*)(red + (ws*16 + c4)*4) = a;
        __syncthreads();
        if (tid < 64) {
            int cg = tid >> 2, j = tid & 3;
            float s = 0.f;
#pragma unroll
            for (int w16 = 0; w16 < 16; w16++) s += red[(w16*16+cg)*4 + j];
            outs[m][tid] = s;
        }
        __syncthreads();
    }
    if (tid < 64) {
        kcb[(long)(b*MAX_ITER + it)*D + h*64 + tid] = kv[tid];
        vcb[(long)(b*MAX_ITER + it)*D + h*64 + tid] = vv[tid];
    }
    __syncthreads();
    if (tid < len) {
        float acc = 0.f;
        if (tid == it) {
#pragma unroll
            for (int d = 0; d < 64; d++) acc += qv[d]*kv[d];
        } else {
            const float* kr = kcb + (long)(b*MAX_ITER + tid)*D + h*64;
            for (int d = 0; d < 64; d++) acc += qv[d]*kr[d];
        }
        p[tid] = acc * 0.125f;
    }
    __syncthreads();
    if (tid == 0) {
        float mx = -1e30f;
        for (int j = 0; j < len; j++) mx = fmaxf(mx, p[j]);
        float sum = 0.f;
        for (int j = 0; j < len; j++) { float e = expf(p[j]-mx); p[j]=e; sum+=e; }
        float r = 1.f/sum;
        for (int j = 0; j < len; j++) p[j] *= r;
    }
    __syncthreads();
    if (tid < 64) {
        float acc = 0.f;
        for (int j = 0; j < len; j++) {
            float vj = (j == it) ? vv[tid]
                     : vcb[(long)(b*MAX_ITER + j)*D + h*64 + tid];
            acc += p[j]*vj;
        }
        csm[tid] = acc;
    }
    __syncthreads();
    if (tid < 128) {
        float4 a = {0,0,0,0};
#pragma unroll 8
        for (int kk = 0; kk < 64; kk++) {
            float4 w = *(const float4*)(so + (long)(h*64+kk)*D + tid*4);
            float cv = csm[kk];
            a.x += cv*w.x; a.y += cv*w.y; a.z += cv*w.z; a.w += cv*w.w;
        }
        *(float4*)(g_sopart + (long)(b*8+h)*D + tid*4) = a;
    }
}

// ---------------- fused cross-attention block (per b,h) ----------------
__device__ void fused_cross(char* sb, const float* cq, const float* co,
                            const float* cK, const float* cV) {
    int t = blockIdx.x;
    if (t >= 32) return;
    int b = t >> 3, h = t & 7;
    const float* xs = (const float*)sb;
    float* KT  = (float*)(sb + 16384);   // 64x64
    float* scr = (float*)(sb + 32768);
    float* qv  = scr;          // 64
    float* p   = qv + 64;      // 64
    float* csm = p + 64;       // 64
    float* red = csm + 64;     // 1024
    int tid = threadIdx.x;
    const float* xb = xs + b * 512;
    {
        int c4 = tid & 15, ws = tid >> 4;
        const float* W = cq + (long)(ws*32)*D + h*64 + c4*4;
        const float* x0 = xb + ws*32;
        float4 a = {0,0,0,0};
#pragma unroll
        for (int kk = 0; kk < 32; kk++) {
            float4 w = *(const float4*)(W + (long)kk*D);
            float x = x0[kk];
            a.x += x*w.x; a.y += x*w.y; a.z += x*w.z; a.w += x*w.w;
        }
        *(float4*)(red + (ws*16 + c4)*4) = a;
    }
    // stage K tile
    for (int i = tid; i < 64*16; i += NT) {
        int j = i >> 4, dg = i & 15;
        *(float4*)(KT + j*64 + dg*4) =
            *(const float4*)(cK + (long)(b*64+j)*D + h*64 + dg*4);
    }
    __syncthreads();
    if (tid < 64) {
        int cg = tid >> 2, j = tid & 3;
        float s = 0.f;
#pragma unroll
        for (int w16 = 0; w16 < 16; w16++) s += red[(w16*16+cg)*4 + j];
        qv[tid] = s;
    }
    __syncthreads();
    if (tid < 64) {
        const float* kr = KT + tid*64;
        float acc = 0.f;
#pragma unroll 16
        for (int d = 0; d < 64; d++) acc += qv[d]*kr[d];
        p[tid] = acc * 0.125f + g_bias[b*64 + tid];
    }
    __syncthreads();
    if (tid == 0) {
        float mx = -1e30f;
        for (int j = 0; j < 64; j++) mx = fmaxf(mx, p[j]);
        float sum = 0.f;
        for (int j = 0; j < 64; j++) { float e = expf(p[j]-mx); p[j]=e; sum+=e; }
        float r = 1.f/sum;
        for (int j = 0; j < 64; j++) p[j] *= r;
    }
    __syncthreads();
    // stage V tile (overwrite KT)
    for (int i = tid; i < 64*16; i += NT) {
        int j = i >> 4, dg = i & 15;
        *(float4*)(KT + j*64 + dg*4) =
            *(const float4*)(cV + (long)(b*64+j)*D + h*64 + dg*4);
    }
    __syncthreads();
    if (tid < 64) {
        float acc = 0.f;
#pragma unroll 16
        for (int j = 0; j < 64; j++) acc += p[j]*KT[j*64 + tid];
        csm[tid] = acc;
    }
    __syncthreads();
    if (tid < 128) {
        float4 a = {0,0,0,0};
#pragma unroll 8
        for (int kk = 0; kk < 64; kk++) {
            float4 w = *(const float4*)(co + (long)(h*64+kk)*D + tid*4);
            float cv = csm[kk];
            a.x += cv*w.x; a.y += cv*w.y; a.z += cv*w.z; a.w += cv*w.w;
        }
        *(float4*)(g_copart + (long)(b*8+h)*D + tid*4) = a;
    }
}

// ---------------- lm_head + exp + partial sum/argmax ----------------
__device__ void lmhead_phase(char* sb, const float* __restrict__ lm,
                             float* out, int it) {
    const float* xs = (const float*)sb;
    float4* red4 = (float4*)(sb + 32768);
    int tid = threadIdx.x;
    int c = tid & 31, ws = tid >> 5;
    for (int cb = blockIdx.x; cb < NCB128; cb += NB) {
        int col0 = cb*128 + c*4;
        const float* Wp = lm + (long)(ws * 64) * V + col0;
        const float* x0 = xs + ws * 64;
        float4 a0 = {0,0,0,0}, a1 = a0, a2 = a0, a3 = a0;
#pragma unroll 16
        for (int kk = 0; kk < 64; kk++) {
            float4 w = *(const float4*)(Wp + (long)kk * V);
            float x0v = x0[kk], x1v = x0[D+kk], x2v = x0[2*D+kk], x3v = x0[3*D+kk];
            a0.x += x0v*w.x; a0.y += x0v*w.y; a0.z += x0v*w.z; a0.w += x0v*w.w;
            a1.x += x1v*w.x; a1.y += x1v*w.y; a1.z += x1v*w.z; a1.w += x1v*w.w;
            a2.x += x2v*w.x; a2.y += x2v*w.y; a2.z += x2v*w.z; a2.w += x2v*w.w;
            a3.x += x3v*w.x; a3.y += x3v*w.y; a3.z += x3v*w.z; a3.w += x3v*w.w;
        }
        int base = (ws*32 + c)*4;
        red4[base+0] = a0; red4[base+1] = a1; red4[base+2] = a2; red4[base+3] = a3;
        __syncthreads();
        if (tid < 128) {
            int cc = tid & 31, b = tid >> 5;
            float4 s = {0,0,0,0};
#pragma unroll
            for (int w8 = 0; w8 < 8; w8++) {
                float4 v = red4[(w8*32 + cc)*4 + b];
                s.x += v.x; s.y += v.y; s.z += v.z; s.w += v.w;
            }
            float4 e;
            e.x = expf(s.x); e.y = expf(s.y); e.z = expf(s.z); e.w = expf(s.w);
            int gcol = cb*128 + cc*4;
            *(float4*)(out + (long)(b*MAX_ITER + it)*V + gcol) = e;
            float ssum = e.x + e.y + e.z + e.w;
            float m = e.x; int mi = gcol;
            if (e.y > m) { m = e.y; mi = gcol+1; }
            if (e.z > m) { m = e.z; mi = gcol+2; }
            if (e.w > m) { m = e.w; mi = gcol+3; }
#pragma unroll
            for (int off = 16; off; off >>= 1) {
                float om = __shfl_xor_sync(0xffffffffu, m, off);
                int omi  = __shfl_xor_sync(0xffffffffu, mi, off);
                float os = __shfl_xor_sync(0xffffffffu, ssum, off);
                ssum += os;
                if (om > m || (om == m && omi < mi)) { m = om; mi = omi; }
            }
            if (cc == 0) {
                g_psum[cb*4 + b] = ssum;
                g_pmax[cb*4 + b] = m;
                g_pidx[cb*4 + b] = mi;
            }
        }
        __syncthreads();
    }
}

// ---------------- e @ emb partials ----------------
__device__ void pe_partial(char* sb, const float* __restrict__ probs,
                           const float* __restrict__ emb, long rstride) {
    float* ps = (float*)sb;
    float4* red4 = (float4*)(sb + 32768);
    int tid = threadIdx.x;
    int c = tid & 31, ws = tid >> 5;
    int t = blockIdx.x;
    int cb = t & 3, kc = t >> 2;
    int len = (kc < PE_KC-1) ? PE_BASE : PE_MAXL;
    int k0 = kc * PE_BASE;
    for (int i = tid; i < 4*len; i += NT) {
        int r = i / len, kk = i % len;
        ps[r*PE_MAXL + kk] = probs[(long)r*rstride + k0 + kk];
    }
    __syncthreads();
    int sl = (len + 7) >> 3;
    int s0 = ws * sl; int s1 = s0 + sl; if (s1 > len) s1 = len;
    int col0 = cb*128 + c*4;
    float4 a0 = {0,0,0,0}, a1 = a0, a2 = a0, a3 = a0;
#pragma unroll 8
    for (int kk = s0; kk < s1; kk++) {
        float4 w = *(const float4*)(emb + (long)(k0 + kk)*D + col0);
        float e0 = ps[kk], e1 = ps[PE_MAXL+kk], e2 = ps[2*PE_MAXL+kk], e3 = ps[3*PE_MAXL+kk];
        a0.x += e0*w.x; a0.y += e0*w.y; a0.z += e0*w.z; a0.w += e0*w.w;
        a1.x += e1*w.x; a1.y += e1*w.y; a1.z += e1*w.z; a1.w += e1*w.w;
        a2.x += e2*w.x; a2.y += e2*w.y; a2.z += e2*w.z; a2.w += e2*w.w;
        a3.x += e3*w.x; a3.y += e3*w.y; a3.z += e3*w.z; a3.w += e3*w.w;
    }
    int base = (ws*32 + c)*4;
    red4[base+0] = a0; red4[base+1] = a1; red4[base+2] = a2; red4[base+3] = a3;
    __syncthreads();
    if (tid < 128) {
        int cc = tid & 31, b = tid >> 5;
        float4 s = {0,0,0,0};
#pragma unroll
        for (int w8 = 0; w8 < 8; w8++) {
            float4 v = red4[(w8*32 + cc)*4 + b];
            s.x += v.x; s.y += v.y; s.z += v.z; s.w += v.w;
        }
        *(float4*)(g_part + ((long)kc*B + b)*D + cb*128 + cc*4) = s;
    }
    __syncthreads();
}

// ---------------- finalize: inv, argmax, next y ----------------
__device__ void finalize_phase(char* sb, int it, int do_pe) {
    if (blockIdx.x >= 12) return;
    int tid = threadIdx.x;
    float* red4 = (float*)(sb + 32768);
    float s0=0.f,s1=0.f,s2=0.f,s3=0.f;
    for (int i = tid; i < NCB128; i += NT) {
        float4 v = *(const float4*)(g_psum + i*4);
        s0 += v.x; s1 += v.y; s2 += v.z; s3 += v.w;
    }
    red4[tid*4+0]=s0; red4[tid*4+1]=s1; red4[tid*4+2]=s2; red4[tid*4+3]=s3;
    __syncthreads();
    for (int o = 128; o; o >>= 1) {
        if (tid < o) {
#pragma unroll
            for (int b = 0; b < 4; b++) red4[tid*4+b] += red4[(tid+o)*4+b];
        }
        __syncthreads();
    }
    float inv[4];
#pragma unroll
    for (int b = 0; b < 4; b++) inv[b] = 1.0f / red4[b];
    __syncthreads();
    if (blockIdx.x < 4) {
        int b = blockIdx.x;
        float* msh = (float*)sb;
        int*   ish = (int*)(sb + 1024);
        float m = -1.0f; int mi = V;
        for (int i = tid; i < NCB128; i += NT) {
            float vm = g_pmax[i*4 + b]; int vi = g_pidx[i*4 + b];
            if (vm > m || (vm == m && vi < mi)) { m = vm; mi = vi; }
        }
        msh[tid] = m; ish[tid] = mi; __syncthreads();
        for (int o = 128; o; o >>= 1) {
            if (tid < o) {
                if (msh[tid+o] > msh[tid] ||
                    (msh[tid+o] == msh[tid] && ish[tid+o] < ish[tid])) {
                    msh[tid] = msh[tid+o]; ish[tid] = ish[tid+o];
                }
            }
            __syncthreads();
        }
        if (tid == 0) g_best[it*4 + b] = ish[0];
        if (blockIdx.x == 0 && tid < 4) g_inv[it*4 + tid] = inv[tid];
    } else if (do_pe) {
        int chunk = blockIdx.x - 4;      // 0..7
        int i = chunk*256 + tid;         // covers 2048
        float s = 0.f;
#pragma unroll
        for (int kc = 0; kc < PE_KC; kc++) s += g_part[(long)kc*B*D + i];
        g_X0[i] = s * inv[i >> 9];
    }
}

// ---------------- megakernel ----------------
__global__ void __launch_bounds__(NT, 1) mega(
    const int* ids, const float* mask, const float* emb,
    const float* enc_wq, const float* enc_wk, const float* enc_wv, const float* enc_wo,
    const float* enc_ln1, const float* enc_w1, const float* enc_w2,
    const float* enc_ln2, const float* enc_lnf,
    const float* dec_sq, const float* dec_sk, const float* dec_sv, const float* dec_so,
    const float* dec_ln1, const float* dec_cq, const float* dec_ck, const float* dec_cv,
    const float* dec_co, const float* dec_ln2, const float* dec_w1, const float* dec_w2,
    const float* dec_ln3, const float* dec_lnf, const float* lm_head, float* out)
{
    __shared__ __align__(16) float sbf[12288];   // 48KB
    char* sb = (char*)sbf;
    int tid = threadIdx.x;

    // ---- init ----
    for (int i = blockIdx.x*NT + tid; i < BS*D; i += NB*NT) {
        int row = i / D, d = i % D;
        g_x[i] = emb[(long)ids[row]*D + d];
    }
    for (int i = blockIdx.x*NT + tid; i < BS; i += NB*NT)
        g_bias[i] = (1.0f - mask[i]) * NEGB;
    for (int i = blockIdx.x*NT + tid; i < B*D; i += NB*NT)
        g_X0[i] = emb[i % D];
    gridbar();

    // ---- encoder ----
    for (int l = 0; l < L; l++) {
        rms_phase(sb, g_x, enc_ln1 + l*D, g_h, BS); gridbar();
        gemm_phase(sb, g_h, enc_wq + (long)l*D*D, 0, g_q, BS, D, D, 0);
        gemm_phase(sb, g_h, enc_wk + (long)l*D*D, 0, g_k, BS, D, D, 0);
        gemm_phase(sb, g_h, enc_wv + (long)l*D*D, 0, g_v, BS, D, D, 0);
        gridbar();
        enc_attn_phase(sb); gridbar();
        gemm_phase(sb, g_ao, enc_wo + (long)l*D*D, g_x, g_x, BS, D, D, 0); gridbar();
        rms_phase(sb, g_x, enc_ln2 + l*D, g_h, BS); gridbar();
        gemm_phase(sb, g_h, enc_w1 + (long)l*D*DFF, 0, g_ff, BS, DFF, D, 1); gridbar();
        gemm_phase(sb, g_ff, enc_w2 + (long)l*DFF*D, g_x, g_x, BS, D, DFF, 0); gridbar();
    }
    rms_phase(sb, g_x, enc_lnf, g_hs, BS); gridbar();
    for (int l = 0; l < L; l++) {
        gemm_phase(sb, g_hs, dec_ck + (long)l*D*D, 0, g_cK + (long)l*BS*D, BS, D, D, 0);
        gemm_phase(sb, g_hs, dec_cv + (long)l*D*D, 0, g_cV + (long)l*BS*D, BS, D, D, 0);
    }
    gridbar();

    // ---- decoder ----
    for (int it = 0; it < MAX_ITER; it++) {
        int len = it + 1;
        for (int l = 0; l < L; l++) {
            const float* Xin = (l == 0) ? g_X0 : g_X1;
            float* Xout      = (l == 0) ? g_X1 : g_X0;
            float* kcb = g_sK + (long)l*B*MAX_ITER*D;
            float* vcb = g_sV + (long)l*B*MAX_ITER*D;
            // P1: rms1 + fused self-attn (+so partials)
            if (blockIdx.x < 32) {
                stage_rms(sb, Xin, dec_ln1 + l*D, 0, 0);
                fused_self(sb, it, len, dec_sq + (long)l*D*D, dec_sk + (long)l*D*D,
                           dec_sv + (long)l*D*D, dec_so + (long)l*D*D, kcb, vcb);
            }
            gridbar();
            // P2: rms2(x+so) + fused cross-attn (+co partials)
            if (blockIdx.x < 32) {
                stage_rms(sb, Xin, dec_ln2 + l*D, g_sopart, 0);
                fused_cross(sb, dec_cq + (long)l*D*D, dec_co + (long)l*D*D,
                            g_cK + (long)l*BS*D, g_cV + (long)l*BS*D);
            }
            gridbar();
            // P3: rms3(x+so+co) + w1
            if (blockIdx.x < 64) {
                stage_rms(sb, Xin, dec_ln3 + l*D, g_sopart, g_copart);
                gemv_mat(sb, D, DFF, dec_w1 + (long)l*D*DFF, g_fft, DFF, 1);
            }
            gridbar();
            // P4: w2 + residual(x+so+co) -> Xout
            if (blockIdx.x < 16) {
                stage_fft(sb);
                gemv_w2(sb, dec_w2 + (long)l*DFF*D, Xin, Xout);
            }
            gridbar();
        }
        // lm head (final X in g_X0)
        stage_rms(sb, g_X0, dec_lnf, 0, 0);
        lmhead_phase(sb, lm_head, out, it); gridbar();
        int do_pe = (it + 1 < MAX_ITER);
        if (do_pe) {
            pe_partial(sb, out + (long)it*V, emb, (long)MAX_ITER*V);
            gridbar();
        }
        finalize_phase(sb, it, do_pe); gridbar();
    }

    // ---- epilogue: normalize probs, write pred flags ----
    {
        float4* outp4 = (float4*)out;
        long total = (long)B*MAX_ITER*(V/4);
        for (long i = blockIdx.x*(long)NT + tid; i < total; i += (long)NB*NT) {
            long row = i / (V/4);
            int b = (int)(row >> 4), it = (int)(row & 15);
            float ib = g_inv[it*4 + b];
            float4 v = outp4[i];
            v.x *= ib; v.y *= ib; v.z *= ib; v.w *= ib;
            outp4[i] = v;
        }
        if (blockIdx.x == 0 && tid < B*MAX_ITER) {
            int b = tid >> 4, it = tid & 15;
            out[(long)B*MAX_ITER*V + b*MAX_ITER + it] =
                (g_best[it*4 + b] == 0) ? 1.0f : 0.0f;
        }
    }
}

// ---------------- host ----------------
extern "C" void kernel_launch(void* const* d_in, const int* in_sizes, int n_in,
                              void* d_out, int out_size) {
    mega<<<NB, NT>>>(
        (const int*)d_in[0], (const float*)d_in[1], (const float*)d_in[2],
        (const float*)d_in[3], (const float*)d_in[4], (const float*)d_in[5],
        (const float*)d_in[6], (const float*)d_in[7], (const float*)d_in[8],
        (const float*)d_in[9], (const float*)d_in[10], (const float*)d_in[11],
        (const float*)d_in[12], (const float*)d_in[13], (const float*)d_in[14],
        (const float*)d_in[15], (const float*)d_in[16], (const float*)d_in[17],
        (const float*)d_in[18], (const float*)d_in[19], (const float*)d_in[20],
        (const float*)d_in[21], (const float*)d_in[22], (const float*)d_in[23],
        (const float*)d_in[24], (const float*)d_in[25], (const float*)d_in[26],
        (float*)d_out);
}

// round 8
// speedup vs baseline: 12.3149x; 1.0383x over previous
#include <cuda_runtime.h>
#include <cuda_bf16.h>
#include <math.h>

#define B 4
#define S 64
#define D 512
#define H 8
#define DH 64
#define DFF 2048
#define L 2
#define V 32128
#define MAX_ITER 16
#define NEGB (-1e9f)
#define BS (B*S)
#define NB 148
#define NT 256
#define NCB128 (V/128)     /* 251 */
#define NSLOT (NCB128*4)   /* 1004 slots (cb x warp) */
#define PE_KC 37
#define PE_BASE 868
#define PE_MAXL 880

// ---------------- device scratch ----------------
__device__ float g_x[BS*D];
__device__ float g_h[BS*D];
__device__ float g_q[BS*D];
__device__ float g_k[BS*D];
__device__ float g_v[BS*D];
__device__ float g_ao[BS*D];
__device__ float g_ff[BS*DFF];
__device__ float g_hs[BS*D];
__device__ float g_cK[L*BS*D];
__device__ float g_cV[L*BS*D];
__device__ float g_sK[L*B*MAX_ITER*D];
__device__ float g_sV[L*B*MAX_ITER*D];
__device__ float g_X0[B*D];
__device__ float g_X1[B*D];
__device__ float g_sopart[B*H*D];
__device__ float g_copart[B*H*D];
__device__ float g_fft[B*DFF];
__device__ float g_bias[BS];
__device__ float g_part[PE_KC*B*D];
__device__ float g_psum[NSLOT*4];
__device__ float g_pmax[NSLOT*4];
__device__ int   g_pidx[NSLOT*4];
__device__ float g_inv[MAX_ITER*4];
__device__ int   g_best[MAX_ITER*4];
__device__ __nv_bfloat16 g_lmhb[(long)D*V];   // bf16 lm_head copy
__device__ __nv_bfloat16 g_embb[(long)V*D];   // bf16 emb copy
__device__ unsigned g_barcnt;
__device__ unsigned g_barsense;

__device__ __forceinline__ unsigned pack2(float lo, float hi) {
    __nv_bfloat162 t = __floats2bfloat162_rn(lo, hi);
    return *reinterpret_cast<unsigned*>(&t);
}
__device__ __forceinline__ void unpack8(const uint4& u, float* w) {
    float2 f;
    f = __bfloat1622float2(*reinterpret_cast<const __nv_bfloat162*>(&u.x)); w[0]=f.x; w[1]=f.y;
    f = __bfloat1622float2(*reinterpret_cast<const __nv_bfloat162*>(&u.y)); w[2]=f.x; w[3]=f.y;
    f = __bfloat1622float2(*reinterpret_cast<const __nv_bfloat162*>(&u.z)); w[4]=f.x; w[5]=f.y;
    f = __bfloat1622float2(*reinterpret_cast<const __nv_bfloat162*>(&u.w)); w[6]=f.x; w[7]=f.y;
}

// ---------------- grid barrier ----------------
__device__ __forceinline__ void gridbar() {
    __syncthreads();
    if (threadIdx.x == 0) {
        __threadfence();
        unsigned cur = *(volatile unsigned*)&g_barsense;
        if (atomicAdd(&g_barcnt, 1u) == NB - 1u) {
            g_barcnt = 0u;
            __threadfence();
            *(volatile unsigned*)&g_barsense = cur + 1u;
        } else {
            while (*(volatile unsigned*)&g_barsense == cur) { __nanosleep(32); }
        }
        __threadfence();
    }
    __syncthreads();
}

// ---------------- encoder tiled GEMM phase ----------------
__device__ void gemm_phase(char* sb, const float* __restrict__ A,
                           const float* __restrict__ W, const float* res,
                           float* C, int M, int N, int K, int relu) {
    float* As = (float*)sb;
    float* Ws = (float*)(sb + 4096);
    int tid = threadIdx.x;
    int n = tid & 31;
    int mg = tid >> 5;
    int tM = M >> 5, tN = N >> 5;
    for (int t = blockIdx.x; t < tM * tN; t += NB) {
        int bm = (t / tN) << 5, bn = (t % tN) << 5;
        float a0=0.f,a1=0.f,a2=0.f,a3=0.f;
        for (int k0 = 0; k0 < K; k0 += 32) {
            {
                int m = (tid*4) >> 5, k = (tid*4) & 31;
                float4 av = *(const float4*)(A + (long)(bm+m)*K + k0 + k);
                As[(k+0)*32 + m] = av.x; As[(k+1)*32 + m] = av.y;
                As[(k+2)*32 + m] = av.z; As[(k+3)*32 + m] = av.w;
            }
            {
                int k = tid >> 3, n4 = (tid & 7) << 2;
                float4 wv = *(const float4*)(W + (long)(k0+k)*N + bn + n4);
                *(float4*)(Ws + k*32 + n4) = wv;
            }
            __syncthreads();
#pragma unroll
            for (int k = 0; k < 32; k++) {
                float w = Ws[k*32 + n];
                a0 += As[k*32 + mg*4+0]*w;
                a1 += As[k*32 + mg*4+1]*w;
                a2 += As[k*32 + mg*4+2]*w;
                a3 += As[k*32 + mg*4+3]*w;
            }
            __syncthreads();
        }
        float accs[4] = {a0,a1,a2,a3};
#pragma unroll
        for (int i = 0; i < 4; i++) {
            long m = bm + mg*4 + i;
            float vv = accs[i];
            if (res)  vv += res[m*N + bn + n];
            if (relu) vv = fmaxf(vv, 0.f);
            C[m*N + bn + n] = vv;
        }
    }
}

// ---------------- RMSNorm phase (encoder rows) ----------------
__device__ void rms_phase(char* sb, const float* in, const float* w,
                          float* out, int rows) {
    float* red = (float*)sb;
    int tid = threadIdx.x;
    for (int r = blockIdx.x; r < rows; r += NB) {
        const float* x = in + (long)r * D;
        float s = 0.f;
        for (int i = tid; i < D; i += NT) { float v = x[i]; s += v*v; }
        red[tid] = s; __syncthreads();
        for (int o = 128; o; o >>= 1) {
            if (tid < o) red[tid] += red[tid+o];
            __syncthreads();
        }
        float inv = rsqrtf(red[0] / (float)D + 1e-6f);
        __syncthreads();
        for (int i = tid; i < D; i += NT)
            out[(long)r*D + i] = x[i] * inv * w[i];
        __syncthreads();
    }
}

// ---------------- encoder attention ----------------
__device__ void enc_attn_phase(char* sb) {
    float* Ks = (float*)sb;
    float* Ps = (float*)(sb + 16384);
    int tid = threadIdx.x;
    for (int t = blockIdx.x; t < B*H; t += NB) {
        int b = t / H, h = t % H;
        for (int i = tid; i < S*DH; i += NT) {
            int j = i / DH, d = i % DH;
            Ks[j*DH + d] = g_k[(long)(b*S + j)*D + h*DH + d];
        }
        __syncthreads();
        for (int i = tid; i < S*S; i += NT) {
            int s = i / S, j = i % S;
            const float* qr = g_q + (long)(b*S + s)*D + h*DH;
            float acc = 0.f;
#pragma unroll
            for (int d = 0; d < DH; d++) acc += qr[d] * Ks[j*DH + d];
            Ps[s*S + j] = acc * 0.125f + g_bias[b*S + j];
        }
        __syncthreads();
        if (tid < S) {
            int s = tid;
            float mx = -1e30f;
            for (int j = 0; j < S; j++) mx = fmaxf(mx, Ps[s*S+j]);
            float sum = 0.f;
            for (int j = 0; j < S; j++) { float e = expf(Ps[s*S+j]-mx); Ps[s*S+j]=e; sum+=e; }
            float r = 1.f / sum;
            for (int j = 0; j < S; j++) Ps[s*S+j] *= r;
        }
        __syncthreads();
        for (int i = tid; i < S*DH; i += NT) {
            int s = i / DH, d = i % DH;
            float acc = 0.f;
            for (int j = 0; j < S; j++)
                acc += Ps[s*S+j] * g_v[(long)(b*S + j)*D + h*DH + d];
            g_ao[(long)(b*S + s)*D + h*DH + d] = acc;
        }
        __syncthreads();
    }
}

// ---------------- decoder stage: xs = rms(X + sum(parts), lnw) ----------------
__device__ void stage_rms(char* sb, const float* X, const float* lnw,
                          const float* part1, const float* part2) {
    float* xs  = (float*)sb;
    float* red = (float*)(sb + 32768);
    int tid = threadIdx.x;
    int base = tid * 8;
    int b = base >> 9;
    int d0 = base & 511;
    float vals[8];
#pragma unroll
    for (int j2 = 0; j2 < 2; j2++) {
        float4 acc = *(const float4*)(X + base + j2*4);
        if (part1) {
#pragma unroll
            for (int h = 0; h < 8; h++) {
                float4 p = *(const float4*)(part1 + (long)(b*8+h)*D + d0 + j2*4);
                acc.x += p.x; acc.y += p.y; acc.z += p.z; acc.w += p.w;
            }
        }
        if (part2) {
#pragma unroll
            for (int h = 0; h < 8; h++) {
                float4 p = *(const float4*)(part2 + (long)(b*8+h)*D + d0 + j2*4);
                acc.x += p.x; acc.y += p.y; acc.z += p.z; acc.w += p.w;
            }
        }
        vals[j2*4+0]=acc.x; vals[j2*4+1]=acc.y; vals[j2*4+2]=acc.z; vals[j2*4+3]=acc.w;
    }
    float s = 0.f;
#pragma unroll
    for (int j = 0; j < 8; j++) s += vals[j]*vals[j];
    red[tid] = s; __syncthreads();
    if (tid < 4) {
        float t = 0.f;
        for (int i = 0; i < 64; i++) t += red[tid*64 + i];
        red[1000 + tid] = rsqrtf(t / 512.0f + 1e-6f);
    }
    __syncthreads();
    float inv = red[1000 + b];
#pragma unroll
    for (int j = 0; j < 8; j++)
        xs[base+j] = vals[j] * inv * lnw[d0 + j];
    __syncthreads();
}

__device__ void stage_fft(char* sb) {
    float4* xs4 = (float4*)sb;
    const float4* f4 = (const float4*)g_fft;
    int tid = threadIdx.x;
    for (int i = tid; i < (4*DFF)/4; i += NT) xs4[i] = f4[i];
    __syncthreads();
}

// ---------------- generic 32-col gemv (used for w1) ----------------
__device__ __forceinline__ void gemv_one(char* sb, int K, int N,
        const float* __restrict__ W, int cb, float* outp, long ostride,
        const float* res, long rstride, int relu) {
    const float* xs = (const float*)sb;
    float4* red4 = (float4*)(sb + 32768);
    int tid = threadIdx.x;
    int c = tid & 7, ws = tid >> 3;
    int Kc = K >> 5;
    int col0 = (cb << 5) + (c << 2);
    const float* Wp = W + (long)(ws * Kc) * N + col0;
    const float* x0 = xs + ws * Kc;
    float4 a0 = {0,0,0,0}, a1 = a0, a2 = a0, a3 = a0;
#pragma unroll 8
    for (int kk = 0; kk < Kc; kk++) {
        float4 w = *(const float4*)(Wp + (long)kk * N);
        float x0v = x0[kk], x1v = x0[K+kk], x2v = x0[2*K+kk], x3v = x0[3*K+kk];
        a0.x += x0v*w.x; a0.y += x0v*w.y; a0.z += x0v*w.z; a0.w += x0v*w.w;
        a1.x += x1v*w.x; a1.y += x1v*w.y; a1.z += x1v*w.z; a1.w += x1v*w.w;
        a2.x += x2v*w.x; a2.y += x2v*w.y; a2.z += x2v*w.z; a2.w += x2v*w.w;
        a3.x += x3v*w.x; a3.y += x3v*w.y; a3.z += x3v*w.z; a3.w += x3v*w.w;
    }
    int base = (ws*8 + c)*4;
    red4[base+0] = a0; red4[base+1] = a1; red4[base+2] = a2; red4[base+3] = a3;
    __syncthreads();
    if (tid < 128) {
        int cc = tid & 31, b = tid >> 5;
        int cg = cc >> 2, j = cc & 3;
        const float* redf = (const float*)red4;
        float s = 0.f;
#pragma unroll
        for (int w32 = 0; w32 < 32; w32++)
            s += redf[((w32*8 + cg)*4 + b)*4 + j];
        int ocol = (cb << 5) + cc;
        if (res)  s += res[(long)b*rstride + ocol];
        if (relu) s = fmaxf(s, 0.f);
        outp[(long)b*ostride + ocol] = s;
    }
    __syncthreads();
}

__device__ void gemv_mat(char* sb, int K, int N, const float* W,
                         float* outp, long ostride, int relu) {
    int ncb = N >> 5;
    for (int cb = blockIdx.x; cb < ncb; cb += NB)
        gemv_one(sb, K, N, W, cb, outp, ostride, 0, 0, relu);
}

// ---------------- w2 gemv with residual-from-partials ----------------
__device__ void gemv_w2(char* sb, const float* __restrict__ W,
                        const float* Xin, float* Xout) {
    const float* xs = (const float*)sb;
    float4* red4 = (float4*)(sb + 32768);
    int tid = threadIdx.x;
    int cb = blockIdx.x;
    int c = tid & 7, ws = tid >> 3;
    int Kc = DFF >> 5;
    int col0 = (cb << 5) + (c << 2);
    const float* Wp = W + (long)(ws * Kc) * D + col0;
    const float* x0 = xs + ws * Kc;
    float4 a0 = {0,0,0,0}, a1 = a0, a2 = a0, a3 = a0;
#pragma unroll 8
    for (int kk = 0; kk < Kc; kk++) {
        float4 w = *(const float4*)(Wp + (long)kk * D);
        float x0v = x0[kk], x1v = x0[DFF+kk], x2v = x0[2*DFF+kk], x3v = x0[3*DFF+kk];
        a0.x += x0v*w.x; a0.y += x0v*w.y; a0.z += x0v*w.z; a0.w += x0v*w.w;
        a1.x += x1v*w.x; a1.y += x1v*w.y; a1.z += x1v*w.z; a1.w += x1v*w.w;
        a2.x += x2v*w.x; a2.y += x2v*w.y; a2.z += x2v*w.z; a2.w += x2v*w.w;
        a3.x += x3v*w.x; a3.y += x3v*w.y; a3.z += x3v*w.z; a3.w += x3v*w.w;
    }
    int base = (ws*8 + c)*4;
    red4[base+0] = a0; red4[base+1] = a1; red4[base+2] = a2; red4[base+3] = a3;
    __syncthreads();
    if (tid < 128) {
        int cc = tid & 31, b = tid >> 5;
        int cg = cc >> 2, j = cc & 3;
        const float* redf = (const float*)red4;
        float s = 0.f;
#pragma unroll
        for (int w32 = 0; w32 < 32; w32++)
            s += redf[((w32*8 + cg)*4 + b)*4 + j];
        int ocol = (cb << 5) + cc;
        float r = Xin[(long)b*D + ocol];
#pragma unroll
        for (int h = 0; h < 8; h++) {
            r += g_sopart[(long)(b*8+h)*D + ocol];
            r += g_copart[(long)(b*8+h)*D + ocol];
        }
        Xout[(long)b*D + ocol] = r + s;
    }
    __syncthreads();
}

// ---------------- fused self-attention block (per b,h) ----------------
__device__ void fused_self(char* sb, int it, int len,
                           const float* sq, const float* sk, const float* sv,
                           const float* so, float* kcb, float* vcb) {
    int t = blockIdx.x;
    if (t >= 32) return;
    int b = t >> 3, h = t & 7;
    const float* xs = (const float*)sb;
    float* scr = (float*)(sb + 32768);
    float* qv  = scr;
    float* kv  = qv + 64;
    float* vv  = kv + 64;
    float* csm = vv + 64;
    float* p   = csm + 64;
    float* red = p + 32;
    int tid = threadIdx.x;
    const float* xb = xs + b * 512;
    int c4 = tid & 15, ws = tid >> 4;
    const float* mats[3] = {sq, sk, sv};
    float* outs[3] = {qv, kv, vv};
#pragma unroll
    for (int m = 0; m < 3; m++) {
        const float* W = mats[m] + (long)(ws*32)*D + h*64 + c4*4;
        const float* x0 = xb + ws*32;
        float4 a = {0,0,0,0};
#pragma unroll
        for (int kk = 0; kk < 32; kk++) {
            float4 w = *(const float4*)(W + (long)kk*D);
            float x = x0[kk];
            a.x += x*w.x; a.y += x*w.y; a.z += x*w.z; a.w += x*w.w;
        }
        *(float4*)(red + (ws*16 + c4)*4) = a;
        __syncthreads();
        if (tid < 64) {
            int cg = tid >> 2, j = tid & 3;
            float s = 0.f;
#pragma unroll
            for (int w16 = 0; w16 < 16; w16++) s += red[(w16*16+cg)*4 + j];
            outs[m][tid] = s;
        }
        __syncthreads();
    }
    if (tid < 64) {
        kcb[(long)(b*MAX_ITER + it)*D + h*64 + tid] = kv[tid];
        vcb[(long)(b*MAX_ITER + it)*D + h*64 + tid] = vv[tid];
    }
    __syncthreads();
    if (tid < len) {
        float acc = 0.f;
        if (tid == it) {
#pragma unroll
            for (int d = 0; d < 64; d++) acc += qv[d]*kv[d];
        } else {
            const float* kr = kcb + (long)(b*MAX_ITER + tid)*D + h*64;
            for (int d = 0; d < 64; d++) acc += qv[d]*kr[d];
        }
        p[tid] = acc * 0.125f;
    }
    __syncthreads();
    if (tid == 0) {
        float mx = -1e30f;
        for (int j = 0; j < len; j++) mx = fmaxf(mx, p[j]);
        float sum = 0.f;
        for (int j = 0; j < len; j++) { float e = expf(p[j]-mx); p[j]=e; sum+=e; }
        float r = 1.f/sum;
        for (int j = 0; j < len; j++) p[j] *= r;
    }
    __syncthreads();
    if (tid < 64) {
        float acc = 0.f;
        for (int j = 0; j < len; j++) {
            float vj = (j == it) ? vv[tid]
                     : vcb[(long)(b*MAX_ITER + j)*D + h*64 + tid];
            acc += p[j]*vj;
        }
        csm[tid] = acc;
    }
    __syncthreads();
    if (tid < 128) {
        float4 a = {0,0,0,0};
#pragma unroll 8
        for (int kk = 0; kk < 64; kk++) {
            float4 w = *(const float4*)(so + (long)(h*64+kk)*D + tid*4);
            float cv = csm[kk];
            a.x += cv*w.x; a.y += cv*w.y; a.z += cv*w.z; a.w += cv*w.w;
        }
        *(float4*)(g_sopart + (long)(b*8+h)*D + tid*4) = a;
    }
}

// ---------------- fused cross-attention block (per b,h) ----------------
__device__ void fused_cross(char* sb, const float* cq, const float* co,
                            const float* cK, const float* cV) {
    int t = blockIdx.x;
    if (t >= 32) return;
    int b = t >> 3, h = t & 7;
    const float* xs = (const float*)sb;
    float* KT  = (float*)(sb + 16384);
    float* scr = (float*)(sb + 32768);
    float* qv  = scr;
    float* p   = qv + 64;
    float* csm = p + 64;
    float* red = csm + 64;
    int tid = threadIdx.x;
    const float* xb = xs + b * 512;
    {
        int c4 = tid & 15, ws = tid >> 4;
        const float* W = cq + (long)(ws*32)*D + h*64 + c4*4;
        const float* x0 = xb + ws*32;
        float4 a = {0,0,0,0};
#pragma unroll
        for (int kk = 0; kk < 32; kk++) {
            float4 w = *(const float4*)(W + (long)kk*D);
            float x = x0[kk];
            a.x += x*w.x; a.y += x*w.y; a.z += x*w.z; a.w += x*w.w;
        }
        *(float4*)(red + (ws*16 + c4)*4) = a;
    }
    for (int i = tid; i < 64*16; i += NT) {
        int j = i >> 4, dg = i & 15;
        *(float4*)(KT + j*64 + dg*4) =
            *(const float4*)(cK + (long)(b*64+j)*D + h*64 + dg*4);
    }
    __syncthreads();
    if (tid < 64) {
        int cg = tid >> 2, j = tid & 3;
        float s = 0.f;
#pragma unroll
        for (int w16 = 0; w16 < 16; w16++) s += red[(w16*16+cg)*4 + j];
        qv[tid] = s;
    }
    __syncthreads();
    if (tid < 64) {
        const float* kr = KT + tid*64;
        float acc = 0.f;
#pragma unroll 16
        for (int d = 0; d < 64; d++) acc += qv[d]*kr[d];
        p[tid] = acc * 0.125f + g_bias[b*64 + tid];
    }
    __syncthreads();
    if (tid == 0) {
        float mx = -1e30f;
        for (int j = 0; j < 64; j++) mx = fmaxf(mx, p[j]);
        float sum = 0.f;
        for (int j = 0; j < 64; j++) { float e = expf(p[j]-mx); p[j]=e; sum+=e; }
        float r = 1.f/sum;
        for (int j = 0; j < 64; j++) p[j] *= r;
    }
    __syncthreads();
    for (int i = tid; i < 64*16; i += NT) {
        int j = i >> 4, dg = i & 15;
        *(float4*)(KT + j*64 + dg*4) =
            *(const float4*)(cV + (long)(b*64+j)*D + h*64 + dg*4);
    }
    __syncthreads();
    if (tid < 64) {
        float acc = 0.f;
#pragma unroll 16
        for (int j = 0; j < 64; j++) acc += p[j]*KT[j*64 + tid];
        csm[tid] = acc;
    }
    __syncthreads();
    if (tid < 128) {
        float4 a = {0,0,0,0};
#pragma unroll 8
        for (int kk = 0; kk < 64; kk++) {
            float4 w = *(const float4*)(co + (long)(h*64+kk)*D + tid*4);
            float cv = csm[kk];
            a.x += cv*w.x; a.y += cv*w.y; a.z += cv*w.z; a.w += cv*w.w;
        }
        *(float4*)(g_copart + (long)(b*8+h)*D + tid*4) = a;
    }
}

// ---------------- lm_head (bf16 x8 loads) + exp + partial sum/argmax --------
__device__ void lmhead_phase(char* sb, float* out, int it) {
    const float* xs = (const float*)sb;
    float* red = (float*)(sb + 32768);    // 4096 floats = 16KB
    int tid = threadIdx.x;
    int c = tid & 15, ws = tid >> 4;      // 16 colgroups x8, 16 K-slices x32
    for (int cb = blockIdx.x; cb < NCB128; cb += NB) {
        int col0 = cb*128 + c*8;
        const __nv_bfloat16* Wp = g_lmhb + (long)(ws*32)*V + col0;
        const float* x0 = xs + ws*32;
        float acc[4][8];
#pragma unroll
        for (int b = 0; b < 4; b++)
#pragma unroll
            for (int j = 0; j < 8; j++) acc[b][j] = 0.f;
#pragma unroll 8
        for (int kk = 0; kk < 32; kk++) {
            uint4 u = *(const uint4*)(Wp + (long)kk*V);
            float w[8]; unpack8(u, w);
            float xv0 = x0[kk], xv1 = x0[D+kk], xv2 = x0[2*D+kk], xv3 = x0[3*D+kk];
#pragma unroll
            for (int j = 0; j < 8; j++) {
                acc[0][j] += xv0*w[j];
                acc[1][j] += xv1*w[j];
                acc[2][j] += xv2*w[j];
                acc[3][j] += xv3*w[j];
            }
        }
        // combine slice pairs (ws, ws^1) within warp
#pragma unroll
        for (int b = 0; b < 4; b++)
#pragma unroll
            for (int j = 0; j < 8; j++)
                acc[b][j] += __shfl_xor_sync(0xffffffffu, acc[b][j], 16);
        if ((tid & 16) == 0) {
            int w = tid >> 5;   // 8 combined slices
#pragma unroll
            for (int b = 0; b < 4; b++)
#pragma unroll
                for (int j = 0; j < 8; j++)
                    red[((w*16 + c)*4 + b)*8 + j] = acc[b][j];
        }
        __syncthreads();
        if (tid < 128) {
            int j = tid, cg = j >> 3, jj = j & 7;
            int gcol = cb*128 + j;
            int lane = tid & 31, w = tid >> 5;   // 4 warps x 32 cols
            float sm[4], mx[4]; int mi[4];
#pragma unroll
            for (int b = 0; b < 4; b++) {
                float s = 0.f;
#pragma unroll
                for (int w8 = 0; w8 < 8; w8++)
                    s += red[((w8*16 + cg)*4 + b)*8 + jj];
                float e = expf(s);
                out[(long)(b*MAX_ITER + it)*V + gcol] = e;
                sm[b] = e; mx[b] = e; mi[b] = gcol;
            }
#pragma unroll
            for (int off = 16; off; off >>= 1) {
#pragma unroll
                for (int b = 0; b < 4; b++) {
                    float om = __shfl_xor_sync(0xffffffffu, mx[b], off);
                    int omi  = __shfl_xor_sync(0xffffffffu, mi[b], off);
                    float os = __shfl_xor_sync(0xffffffffu, sm[b], off);
                    sm[b] += os;
                    if (om > mx[b] || (om == mx[b] && omi < mi[b])) { mx[b] = om; mi[b] = omi; }
                }
            }
            if (lane == 0) {
                int slot = cb*4 + w;
#pragma unroll
                for (int b = 0; b < 4; b++) {
                    g_psum[slot*4 + b] = sm[b];
                    g_pmax[slot*4 + b] = mx[b];
                    g_pidx[slot*4 + b] = mi[b];
                }
            }
        }
        __syncthreads();
    }
}

// ---------------- e @ emb partials (bf16 x8 loads) ----------------
__device__ void pe_partial(char* sb, const float* __restrict__ probs, long rstride) {
    float* ps = (float*)sb;
    float* red = (float*)(sb + 32768);
    int tid = threadIdx.x;
    int c = tid & 15, ws = tid >> 4;
    int t = blockIdx.x;
    int cb = t & 3, kc = t >> 2;
    int len = (kc < PE_KC-1) ? PE_BASE : PE_MAXL;
    int k0 = kc * PE_BASE;
    for (int i = tid; i < 4*len; i += NT) {
        int r = i / len, kk = i % len;
        ps[r*PE_MAXL + kk] = probs[(long)r*rstride + k0 + kk];
    }
    __syncthreads();
    int sl = (len + 15) >> 4;
    int s0 = ws * sl; int s1 = s0 + sl; if (s1 > len) s1 = len;
    int col0 = cb*128 + c*8;
    float acc[4][8];
#pragma unroll
    for (int b = 0; b < 4; b++)
#pragma unroll
        for (int j = 0; j < 8; j++) acc[b][j] = 0.f;
#pragma unroll 8
    for (int kk = s0; kk < s1; kk++) {
        uint4 u = *(const uint4*)(g_embb + (long)(k0 + kk)*D + col0);
        float w[8]; unpack8(u, w);
        float e0 = ps[kk], e1 = ps[PE_MAXL+kk], e2 = ps[2*PE_MAXL+kk], e3 = ps[3*PE_MAXL+kk];
#pragma unroll
        for (int j = 0; j < 8; j++) {
            acc[0][j] += e0*w[j];
            acc[1][j] += e1*w[j];
            acc[2][j] += e2*w[j];
            acc[3][j] += e3*w[j];
        }
    }
#pragma unroll
    for (int b = 0; b < 4; b++)
#pragma unroll
        for (int j = 0; j < 8; j++)
            acc[b][j] += __shfl_xor_sync(0xffffffffu, acc[b][j], 16);
    if ((tid & 16) == 0) {
        int w = tid >> 5;
#pragma unroll
        for (int b = 0; b < 4; b++)
#pragma unroll
            for (int j = 0; j < 8; j++)
                red[((w*16 + c)*4 + b)*8 + j] = acc[b][j];
    }
    __syncthreads();
    if (tid < 128) {
        int j = tid, cg = j >> 3, jj = j & 7;
#pragma unroll
        for (int b = 0; b < 4; b++) {
            float s = 0.f;
#pragma unroll
            for (int w8 = 0; w8 < 8; w8++)
                s += red[((w8*16 + cg)*4 + b)*8 + jj];
            g_part[((long)kc*B + b)*D + cb*128 + j] = s;
        }
    }
    __syncthreads();
}

// ---------------- finalize: inv, argmax, next y ----------------
__device__ void finalize_phase(char* sb, int it, int do_pe) {
    if (blockIdx.x >= 12) return;
    int tid = threadIdx.x;
    float* red4 = (float*)(sb + 32768);
    float s0=0.f,s1=0.f,s2=0.f,s3=0.f;
    for (int i = tid; i < NSLOT; i += NT) {
        float4 v = *(const float4*)(g_psum + i*4);
        s0 += v.x; s1 += v.y; s2 += v.z; s3 += v.w;
    }
    red4[tid*4+0]=s0; red4[tid*4+1]=s1; red4[tid*4+2]=s2; red4[tid*4+3]=s3;
    __syncthreads();
    for (int o = 128; o; o >>= 1) {
        if (tid < o) {
#pragma unroll
            for (int b = 0; b < 4; b++) red4[tid*4+b] += red4[(tid+o)*4+b];
        }
        __syncthreads();
    }
    float inv[4];
#pragma unroll
    for (int b = 0; b < 4; b++) inv[b] = 1.0f / red4[b];
    __syncthreads();
    if (blockIdx.x < 4) {
        int b = blockIdx.x;
        float* msh = (float*)sb;
        int*   ish = (int*)(sb + 1024);
        float m = -1.0f; int mi = V;
        for (int i = tid; i < NSLOT; i += NT) {
            float vm = g_pmax[i*4 + b]; int vi = g_pidx[i*4 + b];
            if (vm > m || (vm == m && vi < mi)) { m = vm; mi = vi; }
        }
        msh[tid] = m; ish[tid] = mi; __syncthreads();
        for (int o = 128; o; o >>= 1) {
            if (tid < o) {
                if (msh[tid+o] > msh[tid] ||
                    (msh[tid+o] == msh[tid] && ish[tid+o] < ish[tid])) {
                    msh[tid] = msh[tid+o]; ish[tid] = ish[tid+o];
                }
            }
            __syncthreads();
        }
        if (tid == 0) g_best[it*4 + b] = ish[0];
        if (blockIdx.x == 0 && tid < 4) g_inv[it*4 + tid] = inv[tid];
    } else if (do_pe) {
        int chunk = blockIdx.x - 4;
        int i = chunk*256 + tid;
        float s = 0.f;
#pragma unroll
        for (int kc = 0; kc < PE_KC; kc++) s += g_part[(long)kc*B*D + i];
        g_X0[i] = s * inv[i >> 9];
    }
}

// ---------------- megakernel ----------------
__global__ void __launch_bounds__(NT, 1) mega(
    const int* ids, const float* mask, const float* emb,
    const float* enc_wq, const float* enc_wk, const float* enc_wv, const float* enc_wo,
    const float* enc_ln1, const float* enc_w1, const float* enc_w2,
    const float* enc_ln2, const float* enc_lnf,
    const float* dec_sq, const float* dec_sk, const float* dec_sv, const float* dec_so,
    const float* dec_ln1, const float* dec_cq, const float* dec_ck, const float* dec_cv,
    const float* dec_co, const float* dec_ln2, const float* dec_w1, const float* dec_w2,
    const float* dec_ln3, const float* dec_lnf, const float* lm_head, float* out)
{
    __shared__ __align__(16) float sbf[12288];
    char* sb = (char*)sbf;
    int tid = threadIdx.x;

    // ---- init + bf16 conversion of lm_head and emb ----
    for (int i = blockIdx.x*NT + tid; i < BS*D; i += NB*NT) {
        int row = i / D, d = i % D;
        g_x[i] = emb[(long)ids[row]*D + d];
    }
    for (int i = blockIdx.x*NT + tid; i < BS; i += NB*NT)
        g_bias[i] = (1.0f - mask[i]) * NEGB;
    for (int i = blockIdx.x*NT + tid; i < B*D; i += NB*NT)
        g_X0[i] = emb[i % D];
    {
        long n8 = ((long)D*V) >> 3;
        const float4* lm4 = (const float4*)lm_head;
        const float4* em4 = (const float4*)emb;
        uint4* lb = (uint4*)g_lmhb;
        uint4* eb = (uint4*)g_embb;
        for (long i = blockIdx.x*(long)NT + tid; i < n8; i += (long)NB*NT) {
            float4 a = lm4[i*2], b = lm4[i*2+1];
            uint4 u;
            u.x = pack2(a.x, a.y); u.y = pack2(a.z, a.w);
            u.z = pack2(b.x, b.y); u.w = pack2(b.z, b.w);
            lb[i] = u;
            float4 cz = em4[i*2], d = em4[i*2+1];
            uint4 v;
            v.x = pack2(cz.x, cz.y); v.y = pack2(cz.z, cz.w);
            v.z = pack2(d.x, d.y); v.w = pack2(d.z, d.w);
            eb[i] = v;
        }
    }
    gridbar();

    // ---- encoder ----
    for (int l = 0; l < L; l++) {
        rms_phase(sb, g_x, enc_ln1 + l*D, g_h, BS); gridbar();
        gemm_phase(sb, g_h, enc_wq + (long)l*D*D, 0, g_q, BS, D, D, 0);
        gemm_phase(sb, g_h, enc_wk + (long)l*D*D, 0, g_k, BS, D, D, 0);
        gemm_phase(sb, g_h, enc_wv + (long)l*D*D, 0, g_v, BS, D, D, 0);
        gridbar();
        enc_attn_phase(sb); gridbar();
        gemm_phase(sb, g_ao, enc_wo + (long)l*D*D, g_x, g_x, BS, D, D, 0); gridbar();
        rms_phase(sb, g_x, enc_ln2 + l*D, g_h, BS); gridbar();
        gemm_phase(sb, g_h, enc_w1 + (long)l*D*DFF, 0, g_ff, BS, DFF, D, 1); gridbar();
        gemm_phase(sb, g_ff, enc_w2 + (long)l*DFF*D, g_x, g_x, BS, D, DFF, 0); gridbar();
    }
    rms_phase(sb, g_x, enc_lnf, g_hs, BS); gridbar();
    for (int l = 0; l < L; l++) {
        gemm_phase(sb, g_hs, dec_ck + (long)l*D*D, 0, g_cK + (long)l*BS*D, BS, D, D, 0);
        gemm_phase(sb, g_hs, dec_cv + (long)l*D*D, 0, g_cV + (long)l*BS*D, BS, D, D, 0);
    }
    gridbar();

    // ---- decoder ----
    for (int it = 0; it < MAX_ITER; it++) {
        int len = it + 1;
        for (int l = 0; l < L; l++) {
            const float* Xin = (l == 0) ? g_X0 : g_X1;
            float* Xout      = (l == 0) ? g_X1 : g_X0;
            float* kcb = g_sK + (long)l*B*MAX_ITER*D;
            float* vcb = g_sV + (long)l*B*MAX_ITER*D;
            if (blockIdx.x < 32) {
                stage_rms(sb, Xin, dec_ln1 + l*D, 0, 0);
                fused_self(sb, it, len, dec_sq + (long)l*D*D, dec_sk + (long)l*D*D,
                           dec_sv + (long)l*D*D, dec_so + (long)l*D*D, kcb, vcb);
            }
            gridbar();
            if (blockIdx.x < 32) {
                stage_rms(sb, Xin, dec_ln2 + l*D, g_sopart, 0);
                fused_cross(sb, dec_cq + (long)l*D*D, dec_co + (long)l*D*D,
                            g_cK + (long)l*BS*D, g_cV + (long)l*BS*D);
            }
            gridbar();
            if (blockIdx.x < 64) {
                stage_rms(sb, Xin, dec_ln3 + l*D, g_sopart, g_copart);
                gemv_mat(sb, D, DFF, dec_w1 + (long)l*D*DFF, g_fft, DFF, 1);
            }
            gridbar();
            if (blockIdx.x < 16) {
                stage_fft(sb);
                gemv_w2(sb, dec_w2 + (long)l*DFF*D, Xin, Xout);
            }
            gridbar();
        }
        stage_rms(sb, g_X0, dec_lnf, 0, 0);
        lmhead_phase(sb, out, it); gridbar();
        int do_pe = (it + 1 < MAX_ITER);
        if (do_pe) {
            pe_partial(sb, out + (long)it*V, (long)MAX_ITER*V);
            gridbar();
        }
        finalize_phase(sb, it, do_pe); gridbar();
    }

    // ---- epilogue: normalize probs, write pred flags ----
    {
        float4* outp4 = (float4*)out;
        long total = (long)B*MAX_ITER*(V/4);
        for (long i = blockIdx.x*(long)NT + tid; i < total; i += (long)NB*NT) {
            long row = i / (V/4);
            int b = (int)(row >> 4), it = (int)(row & 15);
            float ib = g_inv[it*4 + b];
            float4 v = outp4[i];
            v.x *= ib; v.y *= ib; v.z *= ib; v.w *= ib;
            outp4[i] = v;
        }
        if (blockIdx.x == 0 && tid < B*MAX_ITER) {
            int b = tid >> 4, it = tid & 15;
            out[(long)B*MAX_ITER*V + b*MAX_ITER + it] =
                (g_best[it*4 + b] == 0) ? 1.0f : 0.0f;
        }
    }
}

// ---------------- host ----------------
extern "C" void kernel_launch(void* const* d_in, const int* in_sizes, int n_in,
                              void* d_out, int out_size) {
    mega<<<NB, NT>>>(
        (const int*)d_in[0], (const float*)d_in[1], (const float*)d_in[2],
        (const float*)d_in[3], (const float*)d_in[4], (const float*)d_in[5],
        (const float*)d_in[6], (const float*)d_in[7], (const float*)d_in[8],
        (const float*)d_in[9], (const float*)d_in[10], (const float*)d_in[11],
        (const float*)d_in[12], (const float*)d_in[13], (const float*)d_in[14],
        (const float*)d_in[15], (const float*)d_in[16], (const float*)d_in[17],
        (const float*)d_in[18], (const float*)d_in[19], (const float*)d_in[20],
        (const float*)d_in[21], (const float*)d_in[22], (const float*)d_in[23],
        (const float*)d_in[24], (const float*)d_in[25], (const float*)d_in[26],
        (float*)d_out);
}